// round 2
// baseline (speedup 1.0000x reference)
#include <cuda_runtime.h>

#define BATCH 16
#define NN    2048
#define TT    12
#define DD    64
#define EE    16
#define BTT   192            // BATCH * TT
#define COLS  12288          // BTT * DD

// ---------------- scratch (static device globals; no runtime allocation) ----
__device__ float g_S [NN * NN];                 // supports [N,N]
__device__ float g_X [(size_t)NN * COLS];       // xr as [N, BT*D]
__device__ float g_Y1[(size_t)NN * COLS];       // S @ X
__device__ float g_Y2[(size_t)NN * COLS];       // S @ Y1

// ---------------- kernel 1: supports = softmax(relu(E E^T), axis=1) --------
__global__ __launch_bounds__(256)
void support_kernel(const float* __restrict__ emb, float* __restrict__ S) {
    const int n   = blockIdx.x;
    const int tid = threadIdx.x;

    const float4* er = (const float4*)(emb + n * EE);
    const float4 e0 = er[0], e1 = er[1], e2 = er[2], e3 = er[3];

    float v[8];
    float mx = -1e30f;
    #pragma unroll
    for (int jj = 0; jj < 8; ++jj) {
        const int m = jj * 256 + tid;
        const float4* fm = (const float4*)(emb + m * EE);
        const float4 f0 = fm[0], f1 = fm[1], f2 = fm[2], f3 = fm[3];
        float d = e0.x*f0.x + e0.y*f0.y + e0.z*f0.z + e0.w*f0.w
                + e1.x*f1.x + e1.y*f1.y + e1.z*f1.z + e1.w*f1.w
                + e2.x*f2.x + e2.y*f2.y + e2.z*f2.z + e2.w*f2.w
                + e3.x*f3.x + e3.y*f3.y + e3.z*f3.z + e3.w*f3.w;
        d = fmaxf(d, 0.0f);
        v[jj] = d;
        mx = fmaxf(mx, d);
    }

    __shared__ float red[256];
    red[tid] = mx;
    __syncthreads();
    for (int s = 128; s > 0; s >>= 1) {
        if (tid < s) red[tid] = fmaxf(red[tid], red[tid + s]);
        __syncthreads();
    }
    mx = red[0];
    __syncthreads();

    float sum = 0.0f;
    #pragma unroll
    for (int jj = 0; jj < 8; ++jj) {
        v[jj] = expf(v[jj] - mx);
        sum += v[jj];
    }
    red[tid] = sum;
    __syncthreads();
    for (int s = 128; s > 0; s >>= 1) {
        if (tid < s) red[tid] += red[tid + s];
        __syncthreads();
    }
    const float inv = 1.0f / red[0];

    #pragma unroll
    for (int jj = 0; jj < 8; ++jj)
        S[(size_t)n * NN + jj * 256 + tid] = v[jj] * inv;
}

// ---------------- kernel 2: x[B,N,T,D] -> X[N, (b*T+t)*D + d] --------------
__global__ __launch_bounds__(256)
void reshape_kernel(const float* __restrict__ x, float* __restrict__ X) {
    const int idx4 = blockIdx.x * blockDim.x + threadIdx.x;   // float4 index
    const int total4 = NN * (COLS / 4);
    if (idx4 >= total4) return;
    const int dv   = idx4 & 15;           // D/4 = 16
    const int rest = idx4 >> 4;
    const int bt   = rest % BTT;
    const int n    = rest / BTT;
    const int b    = bt / TT;
    const int t    = bt % TT;
    const size_t in4 = ((size_t)(b * NN + n) * TT + t) * 16 + dv;
    ((float4*)X)[idx4] = ((const float4*)x)[in4];
}

// ---------------- kernel 3/4: C[M,Ncols] = A[M,K] * B[K,Ncols] (fp32) ------
#define BM 128
#define BN 128
#define BK 8
#define TM 8
#define TN 8

__global__ __launch_bounds__(256)
void sgemm_kernel(const float* __restrict__ A, const float* __restrict__ B,
                  float* __restrict__ C, int Kdim, int Ncols) {
    __shared__ float As[BK][BM];
    __shared__ float Bs[BK][BN];

    const int tid  = threadIdx.x;
    const int bcol = blockIdx.x;   // over Ncols
    const int brow = blockIdx.y;   // over M

    const float* Ablk = A + (size_t)brow * BM * Kdim;
    const float* Bblk = B + (size_t)bcol * BN;

    const int arow   = tid >> 1;          // 0..127
    const int acol   = (tid & 1) << 2;    // 0 or 4
    const int brw    = tid >> 5;          // 0..7
    const int bcl    = (tid & 31) << 2;   // 0..124
    const int ty     = tid >> 4;          // 0..15
    const int tx     = tid & 15;          // 0..15

    float acc[TM][TN];
    #pragma unroll
    for (int i = 0; i < TM; ++i)
        #pragma unroll
        for (int j = 0; j < TN; ++j) acc[i][j] = 0.0f;

    for (int k0 = 0; k0 < Kdim; k0 += BK) {
        const float4 a = *(const float4*)(Ablk + (size_t)arow * Kdim + k0 + acol);
        As[acol + 0][arow] = a.x;
        As[acol + 1][arow] = a.y;
        As[acol + 2][arow] = a.z;
        As[acol + 3][arow] = a.w;
        *(float4*)(&Bs[brw][bcl]) =
            *(const float4*)(Bblk + (size_t)(k0 + brw) * Ncols + bcl);
        __syncthreads();

        #pragma unroll
        for (int k = 0; k < BK; ++k) {
            float af[TM], bf[TN];
            *(float4*)(&af[0]) = *(const float4*)(&As[k][ty * TM]);
            *(float4*)(&af[4]) = *(const float4*)(&As[k][ty * TM + 4]);
            *(float4*)(&bf[0]) = *(const float4*)(&Bs[k][tx * TN]);
            *(float4*)(&bf[4]) = *(const float4*)(&Bs[k][tx * TN + 4]);
            #pragma unroll
            for (int i = 0; i < TM; ++i)
                #pragma unroll
                for (int j = 0; j < TN; ++j)
                    acc[i][j] = fmaf(af[i], bf[j], acc[i][j]);
        }
        __syncthreads();
    }

    #pragma unroll
    for (int i = 0; i < TM; ++i) {
        const size_t row = (size_t)brow * BM + ty * TM + i;
        float* cp = C + row * Ncols + bcol * BN + tx * TN;
        *(float4*)(cp)     = make_float4(acc[i][0], acc[i][1], acc[i][2], acc[i][3]);
        *(float4*)(cp + 4) = make_float4(acc[i][4], acc[i][5], acc[i][6], acc[i][7]);
    }
}

// ---------------- kernel 5: per-node hypernet weights + grouped GEMM -------
// smem: W[3*64*64] + A0/A1/A2 padded [192*65] + bias[64] + En[16]
#define APAD 65
#define FINAL_SMEM_FLOATS (12288 + 3 * (BTT * APAD) + DD + EE)
#define FINAL_SMEM_BYTES  (FINAL_SMEM_FLOATS * 4)

__global__ __launch_bounds__(256)
void final_kernel(const float* __restrict__ emb, const float* __restrict__ wp,
                  const float* __restrict__ bp,  const float* __restrict__ X,
                  const float* __restrict__ Y1,  const float* __restrict__ Y2,
                  float* __restrict__ out) {
    extern __shared__ float fsm[];
    float* Wsm  = fsm;                    // 12288  (k*4096 + i*64 + o)
    float* A0   = Wsm + 12288;            // 192*65
    float* A1   = A0 + BTT * APAD;
    float* A2   = A1 + BTT * APAD;
    float* bias = A2 + BTT * APAD;        // 64
    float* En   = bias + DD;              // 16

    const int n   = blockIdx.x;
    const int tid = threadIdx.x;

    if (tid < EE) En[tid] = emb[n * EE + tid];
    __syncthreads();

    // W[n] = sum_e En[e] * Wp[e, :]
    for (int j = tid; j < 12288; j += 256) {
        float s = 0.0f;
        #pragma unroll
        for (int e = 0; e < EE; ++e)
            s = fmaf(En[e], wp[e * 12288 + j], s);
        Wsm[j] = s;
    }
    if (tid < DD) {
        float s = 0.0f;
        #pragma unroll
        for (int e = 0; e < EE; ++e)
            s = fmaf(En[e], bp[e * DD + tid], s);
        bias[tid] = s;
    }

    // stage activations: A0 = X row, A1 = (S X) row, A2 = 2*(S S X) - X row
    const float* Xr  = X  + (size_t)n * COLS;
    const float* Y1r = Y1 + (size_t)n * COLS;
    const float* Y2r = Y2 + (size_t)n * COLS;
    for (int j = tid; j < COLS; j += 256) {
        const int r = j >> 6, c = j & 63;
        const float xv = Xr[j];
        A0[r * APAD + c] = xv;
        A1[r * APAD + c] = Y1r[j];
        A2[r * APAD + c] = 2.0f * Y2r[j] - xv;
    }
    __syncthreads();

    // grouped GEMM: out[bt, o] = sum_k sum_i Ak[bt,i] * Wk[i,o] + bias[o]
    const int rg = tid >> 3;        // 0..31  -> rows r0..r0+5
    const int cg = tid & 7;         // 0..7   -> cols c0..c0+7
    const int r0 = rg * 6;
    const int c0 = cg * 8;

    float acc[6][8];
    #pragma unroll
    for (int rr = 0; rr < 6; ++rr)
        #pragma unroll
        for (int j = 0; j < 8; ++j) acc[rr][j] = bias[c0 + j];

    #pragma unroll
    for (int k = 0; k < 3; ++k) {
        const float* Ak = (k == 0) ? A0 : (k == 1) ? A1 : A2;
        const float* Wk = Wsm + k * 4096;
        #pragma unroll 4
        for (int i = 0; i < DD; ++i) {
            float w[8];
            #pragma unroll
            for (int j = 0; j < 8; ++j) w[j] = Wk[i * DD + c0 + j];
            #pragma unroll
            for (int rr = 0; rr < 6; ++rr) {
                const float a = Ak[(r0 + rr) * APAD + i];
                #pragma unroll
                for (int j = 0; j < 8; ++j)
                    acc[rr][j] = fmaf(a, w[j], acc[rr][j]);
            }
        }
    }

    #pragma unroll
    for (int rr = 0; rr < 6; ++rr) {
        const int r = r0 + rr;
        const int b = r / TT, t = r % TT;
        float* op = out + ((size_t)(b * NN + n) * TT + t) * DD + c0;
        *(float4*)(op)     = make_float4(acc[rr][0], acc[rr][1], acc[rr][2], acc[rr][3]);
        *(float4*)(op + 4) = make_float4(acc[rr][4], acc[rr][5], acc[rr][6], acc[rr][7]);
    }
}

// ---------------- launcher -------------------------------------------------
extern "C" void kernel_launch(void* const* d_in, const int* in_sizes, int n_in,
                              void* d_out, int out_size) {
    const float* x   = (const float*)d_in[0];   // [B,N,T,D]
    const float* emb = (const float*)d_in[1];   // [N,E]
    const float* wp  = (const float*)d_in[2];   // [E,K,D,D]
    const float* bp  = (const float*)d_in[3];   // [E,D]
    float* out = (float*)d_out;                 // [B,N,T,D]

    float *S, *X, *Y1, *Y2;
    cudaGetSymbolAddress((void**)&S,  g_S);
    cudaGetSymbolAddress((void**)&X,  g_X);
    cudaGetSymbolAddress((void**)&Y1, g_Y1);
    cudaGetSymbolAddress((void**)&Y2, g_Y2);

    cudaFuncSetAttribute(final_kernel,
                         cudaFuncAttributeMaxDynamicSharedMemorySize,
                         FINAL_SMEM_BYTES);

    support_kernel<<<NN, 256>>>(emb, S);

    const int total4 = NN * (COLS / 4);
    reshape_kernel<<<(total4 + 255) / 256, 256>>>(x, X);

    dim3 gemm_grid(COLS / BN, NN / BM);
    sgemm_kernel<<<gemm_grid, 256>>>(S, X,  Y1, NN, COLS);
    sgemm_kernel<<<gemm_grid, 256>>>(S, Y1, Y2, NN, COLS);

    final_kernel<<<NN, 256, FINAL_SMEM_BYTES>>>(emb, wp, bp, X, Y1, Y2, out);
}

// round 10
// speedup vs baseline: 4.3868x; 4.3868x over previous
#include <cuda_runtime.h>
#include <cuda_bf16.h>
#include <cstdint>

#define BATCH 16
#define NN    2048
#define TT    12
#define DD    64
#define EE    16
#define BTT   192            // BATCH * TT
#define COLS  12288          // BTT * DD

// ---------------- scratch (static device globals) --------------------------
__device__ __nv_bfloat16 g_Shi[(size_t)NN * NN];        // S hi  [N,N]
__device__ __nv_bfloat16 g_Slo[(size_t)NN * NN];        // S lo
__device__ float         g_X  [(size_t)NN * COLS];      // xr as [N, BT*D]
__device__ __nv_bfloat16 g_Bhi[(size_t)COLS * NN];      // transposed operand hi
__device__ __nv_bfloat16 g_Blo[(size_t)COLS * NN];      // transposed operand lo
__device__ float         g_Y1 [(size_t)NN * COLS];      // S @ X
__device__ float         g_Y2 [(size_t)NN * COLS];      // S @ Y1

// ==================== helpers (baseline PTX only, safe on sm_103) ==========
__device__ __forceinline__ uint32_t smem_to_u32(const void* p) {
    uint32_t a;
    asm("{ .reg .u64 t; cvta.to.shared.u64 t, %1; cvt.u32.u64 %0, t; }"
        : "=r"(a) : "l"(p));
    return a;
}

// SW128 swizzle for 128-byte rows: bits[6:4] ^= bits[9:7]  (conflict-free)
__device__ __forceinline__ uint32_t swz128(uint32_t o) {
    return o ^ ((o >> 3) & 0x70u);
}

__device__ __forceinline__ void cp_async16(uint32_t saddr, const void* gaddr) {
    asm volatile("cp.async.cg.shared.global [%0], [%1], 16;"
                 :: "r"(saddr), "l"(gaddr));
}
#define CP_COMMIT() asm volatile("cp.async.commit_group;")
#define CP_WAIT2()  asm volatile("cp.async.wait_group 2;")

__device__ __forceinline__ void ldmx4(uint32_t r[4], uint32_t addr) {
    asm volatile("ldmatrix.sync.aligned.m8n8.x4.shared.b16 {%0,%1,%2,%3}, [%4];"
                 : "=r"(r[0]), "=r"(r[1]), "=r"(r[2]), "=r"(r[3]) : "r"(addr));
}

__device__ __forceinline__ void mma_bf16(float4& d, const uint32_t a[4],
                                         const uint32_t b[2]) {
    asm volatile(
        "mma.sync.aligned.m16n8k16.row.col.f32.bf16.bf16.f32 "
        "{%0,%1,%2,%3}, {%4,%5,%6,%7}, {%8,%9}, {%0,%1,%2,%3};"
        : "+f"(d.x), "+f"(d.y), "+f"(d.z), "+f"(d.w)
        : "r"(a[0]), "r"(a[1]), "r"(a[2]), "r"(a[3]), "r"(b[0]), "r"(b[1]));
}

// ---------------- kernel 1: supports = softmax(relu(E E^T)) -> hi/lo bf16 --
__global__ __launch_bounds__(256)
void support_kernel(const float* __restrict__ emb,
                    __nv_bfloat16* __restrict__ Shi,
                    __nv_bfloat16* __restrict__ Slo) {
    const int n   = blockIdx.x;
    const int tid = threadIdx.x;

    const float4* er = (const float4*)(emb + n * EE);
    const float4 e0 = er[0], e1 = er[1], e2 = er[2], e3 = er[3];

    float v[8];
    float mx = -1e30f;
    #pragma unroll
    for (int jj = 0; jj < 8; ++jj) {
        const int m = jj * 256 + tid;
        const float4* fm = (const float4*)(emb + m * EE);
        const float4 f0 = fm[0], f1 = fm[1], f2 = fm[2], f3 = fm[3];
        float d = e0.x*f0.x + e0.y*f0.y + e0.z*f0.z + e0.w*f0.w
                + e1.x*f1.x + e1.y*f1.y + e1.z*f1.z + e1.w*f1.w
                + e2.x*f2.x + e2.y*f2.y + e2.z*f2.z + e2.w*f2.w
                + e3.x*f3.x + e3.y*f3.y + e3.z*f3.z + e3.w*f3.w;
        d = fmaxf(d, 0.0f);
        v[jj] = d;
        mx = fmaxf(mx, d);
    }

    __shared__ float red[256];
    red[tid] = mx;
    __syncthreads();
    for (int s = 128; s > 0; s >>= 1) {
        if (tid < s) red[tid] = fmaxf(red[tid], red[tid + s]);
        __syncthreads();
    }
    mx = red[0];
    __syncthreads();

    float sum = 0.0f;
    #pragma unroll
    for (int jj = 0; jj < 8; ++jj) {
        v[jj] = expf(v[jj] - mx);
        sum += v[jj];
    }
    red[tid] = sum;
    __syncthreads();
    for (int s = 128; s > 0; s >>= 1) {
        if (tid < s) red[tid] += red[tid + s];
        __syncthreads();
    }
    const float inv = 1.0f / red[0];

    #pragma unroll
    for (int jj = 0; jj < 8; ++jj) {
        const float val = v[jj] * inv;
        const __nv_bfloat16 h = __float2bfloat16(val);
        const size_t o = (size_t)n * NN + jj * 256 + tid;
        Shi[o] = h;
        Slo[o] = __float2bfloat16(val - __bfloat162float(h));
    }
}

// ---------------- kernel 2: x[B,N,T,D] -> X[N, (b*T+t)*D + d] --------------
__global__ __launch_bounds__(256)
void reshape_kernel(const float* __restrict__ x, float* __restrict__ X) {
    const int idx4 = blockIdx.x * blockDim.x + threadIdx.x;   // float4 index
    const int total4 = NN * (COLS / 4);
    if (idx4 >= total4) return;
    const int dv   = idx4 & 15;           // D/4 = 16
    const int rest = idx4 >> 4;
    const int bt   = rest % BTT;
    const int n    = rest / BTT;
    const int b    = bt / TT;
    const int t    = bt % TT;
    const size_t in4 = ((size_t)(b * NN + n) * TT + t) * 16 + dv;
    ((float4*)X)[idx4] = ((const float4*)x)[in4];
}

// ---------------- kernel 3: transpose + hi/lo split ------------------------
// in [NN, COLS] fp32  ->  hi/lo [COLS, NN] bf16
__global__ __launch_bounds__(256)
void tsplit_kernel(const float* __restrict__ in,
                   __nv_bfloat16* __restrict__ hi,
                   __nv_bfloat16* __restrict__ lo) {
    __shared__ float tile[32][33];
    const int tx = threadIdx.x & 31;
    const int ty = threadIdx.x >> 5;     // 0..7
    const int c0 = blockIdx.x * 32;      // over COLS
    const int r0 = blockIdx.y * 32;      // over NN
    #pragma unroll
    for (int j = 0; j < 4; ++j)
        tile[ty + j * 8][tx] = in[(size_t)(r0 + ty + j * 8) * COLS + c0 + tx];
    __syncthreads();
    #pragma unroll
    for (int j = 0; j < 4; ++j) {
        const int c = ty + j * 8;
        const float v = tile[tx][c];
        const __nv_bfloat16 h = __float2bfloat16(v);
        const size_t o = (size_t)(c0 + c) * NN + r0 + tx;
        hi[o] = h;
        lo[o] = __float2bfloat16(v - __bfloat162float(h));
    }
}

// ---------------- kernel 4/5: mma.sync GEMM  C = A * B^T -------------------
// A (hi/lo): [2048,2048] bf16, K-contiguous rows.
// B (hi/lo): [12288,2048] bf16, K-contiguous rows.
// C: [2048,12288] fp32.
// CTA tile 128x128, BK=32, 3-stage cp.async pipeline, 8 warps 64x32.
// Smem row layout per operand row r: [hi(k0..k0+31) | lo(k0..k0+31)] = 128 B,
// SW128-swizzled -> conflict-free ldmatrix for both hi and lo halves.
#define STG_BYTES 32768            // A 16KB + B 16KB
#define OFF_A 0
#define OFF_B 16384
#define NSTAGE 3
#define GEMM_SMEM_BYTES (NSTAGE * STG_BYTES)   // 98304

__device__ __forceinline__ void load_stage(
    uint32_t sbase, int buf,
    const __nv_bfloat16* __restrict__ Ah, const __nv_bfloat16* __restrict__ Al,
    const __nv_bfloat16* __restrict__ Bh, const __nv_bfloat16* __restrict__ Bl,
    int m0, int n0, int k0, int tid)
{
    const int row = tid >> 3;            // 0..31
    const int ch  = tid & 7;             // 16B chunk within 128B row
    const int kc  = (ch & 3) * 8;        // k-element offset within 32
    const bool lo = (ch >= 4);
    const uint32_t st = sbase + buf * STG_BYTES;
    const __nv_bfloat16* Asrc = lo ? Al : Ah;
    const __nv_bfloat16* Bsrc = lo ? Bl : Bh;
    #pragma unroll
    for (int h = 0; h < 4; ++h) {
        const int r = row + h * 32;      // 0..127
        const uint32_t so = swz128((uint32_t)(r * 128 + ch * 16));
        cp_async16(st + OFF_A + so, Asrc + (size_t)(m0 + r) * NN + k0 + kc);
        cp_async16(st + OFF_B + so, Bsrc + (size_t)(n0 + r) * NN + k0 + kc);
    }
}

__global__ __launch_bounds__(256)
void mma_gemm_kernel(const __nv_bfloat16* __restrict__ Ah,
                     const __nv_bfloat16* __restrict__ Al,
                     const __nv_bfloat16* __restrict__ Bh,
                     const __nv_bfloat16* __restrict__ Bl,
                     float* __restrict__ C) {
    extern __shared__ __align__(1024) char smem[];
    const uint32_t sbase = smem_to_u32(smem);
    const int tid  = threadIdx.x;
    const int lane = tid & 31;
    const int wid  = tid >> 5;
    const int wm   = wid & 1;            // 2 warps over M
    const int wn   = wid >> 1;           // 4 warps over N
    const int n0   = blockIdx.x * 128;   // grid.x over COLS (96) -> fills wave 1
    const int m0   = blockIdx.y * 128;   // grid.y over M (16)

    // ldmatrix lane->row/khalf maps
    const int lr_a = lane & 15;                          // A: row within 16
    const int kh_a = lane >> 4;                          // A: k-half
    const int lr_b = (lane & 7) | ((lane & 16) >> 1);    // B: row within 16
    const int kh_b = (lane >> 3) & 1;                    // B: k-half

    float4 acc[4][4];
    #pragma unroll
    for (int i = 0; i < 4; ++i)
        #pragma unroll
        for (int j = 0; j < 4; ++j) acc[i][j] = make_float4(0.f, 0.f, 0.f, 0.f);

    #pragma unroll
    for (int s = 0; s < NSTAGE; ++s) {
        load_stage(sbase, s, Ah, Al, Bh, Bl, m0, n0, s * 32, tid);
        CP_COMMIT();
    }

    const int NITER = NN / 32;           // 64
    int buf = 0;
    for (int it = 0; it < NITER; ++it) {
        CP_WAIT2();
        __syncthreads();

        const uint32_t st = sbase + buf * STG_BYTES;
        #pragma unroll
        for (int ks = 0; ks < 2; ++ks) {
            uint32_t ah[4][4], al[4][4], bh[4][2], bl[4][2];
            #pragma unroll
            for (int mi = 0; mi < 4; ++mi) {
                const int r = wm * 64 + mi * 16 + lr_a;
                const uint32_t base = (uint32_t)(r * 128 + ks * 32 + kh_a * 16);
                ldmx4(ah[mi], st + OFF_A + swz128(base));
                ldmx4(al[mi], st + OFF_A + swz128(base + 64u));
            }
            #pragma unroll
            for (int nt = 0; nt < 2; ++nt) {
                const int r = wn * 32 + nt * 16 + lr_b;
                const uint32_t base = (uint32_t)(r * 128 + ks * 32 + kh_b * 16);
                uint32_t t[4];
                ldmx4(t, st + OFF_B + swz128(base));
                bh[nt * 2][0] = t[0]; bh[nt * 2][1] = t[1];
                bh[nt * 2 + 1][0] = t[2]; bh[nt * 2 + 1][1] = t[3];
                ldmx4(t, st + OFF_B + swz128(base + 64u));
                bl[nt * 2][0] = t[0]; bl[nt * 2][1] = t[1];
                bl[nt * 2 + 1][0] = t[2]; bl[nt * 2 + 1][1] = t[3];
            }
            // 3 products (hi*hi + hi*lo + lo*hi)
            #pragma unroll
            for (int mi = 0; mi < 4; ++mi)
                #pragma unroll
                for (int nj = 0; nj < 4; ++nj)
                    mma_bf16(acc[mi][nj], ah[mi], bh[nj]);
            #pragma unroll
            for (int mi = 0; mi < 4; ++mi)
                #pragma unroll
                for (int nj = 0; nj < 4; ++nj)
                    mma_bf16(acc[mi][nj], ah[mi], bl[nj]);
            #pragma unroll
            for (int mi = 0; mi < 4; ++mi)
                #pragma unroll
                for (int nj = 0; nj < 4; ++nj)
                    mma_bf16(acc[mi][nj], al[mi], bh[nj]);
        }
        __syncthreads();

        if (it + NSTAGE < NITER)
            load_stage(sbase, buf, Ah, Al, Bh, Bl, m0, n0, (it + NSTAGE) * 32, tid);
        CP_COMMIT();                     // empty commits at tail keep counts sane

        buf = (buf + 1 == NSTAGE) ? 0 : buf + 1;
    }

    // epilogue
    const int g  = lane >> 2;
    const int id = lane & 3;
    #pragma unroll
    for (int mi = 0; mi < 4; ++mi) {
        const int row = m0 + wm * 64 + mi * 16 + g;
        #pragma unroll
        for (int nj = 0; nj < 4; ++nj) {
            const int col = n0 + wn * 32 + nj * 8 + id * 2;
            float2* p0 = (float2*)(C + (size_t)row * COLS + col);
            float2* p1 = (float2*)(C + (size_t)(row + 8) * COLS + col);
            *p0 = make_float2(acc[mi][nj].x, acc[mi][nj].y);
            *p1 = make_float2(acc[mi][nj].z, acc[mi][nj].w);
        }
    }
}

// ---------------- kernel 6: per-node hypernet weights + grouped GEMM -------
#define APAD 65
#define FINAL_SMEM_FLOATS (12288 + 3 * (BTT * APAD) + DD + EE)
#define FINAL_SMEM_BYTES  (FINAL_SMEM_FLOATS * 4)

__global__ __launch_bounds__(256)
void final_kernel(const float* __restrict__ emb, const float* __restrict__ wp,
                  const float* __restrict__ bp,  const float* __restrict__ X,
                  const float* __restrict__ Y1,  const float* __restrict__ Y2,
                  float* __restrict__ out) {
    extern __shared__ float fsm[];
    float* Wsm  = fsm;                    // 12288  (k*4096 + i*64 + o)
    float* A0   = Wsm + 12288;            // 192*65
    float* A1   = A0 + BTT * APAD;
    float* A2   = A1 + BTT * APAD;
    float* bias = A2 + BTT * APAD;        // 64
    float* En   = bias + DD;              // 16

    const int n   = blockIdx.x;
    const int tid = threadIdx.x;

    if (tid < EE) En[tid] = emb[n * EE + tid];
    __syncthreads();

    for (int j = tid; j < 12288; j += 256) {
        float s = 0.0f;
        #pragma unroll
        for (int e = 0; e < EE; ++e)
            s = fmaf(En[e], wp[e * 12288 + j], s);
        Wsm[j] = s;
    }
    if (tid < DD) {
        float s = 0.0f;
        #pragma unroll
        for (int e = 0; e < EE; ++e)
            s = fmaf(En[e], bp[e * DD + tid], s);
        bias[tid] = s;
    }

    const float* Xr  = X  + (size_t)n * COLS;
    const float* Y1r = Y1 + (size_t)n * COLS;
    const float* Y2r = Y2 + (size_t)n * COLS;
    for (int j = tid; j < COLS; j += 256) {
        const int r = j >> 6, c = j & 63;
        const float xv = Xr[j];
        A0[r * APAD + c] = xv;
        A1[r * APAD + c] = Y1r[j];
        A2[r * APAD + c] = 2.0f * Y2r[j] - xv;
    }
    __syncthreads();

    const int rg = tid >> 3;        // 0..31  -> rows r0..r0+5
    const int cg = tid & 7;         // 0..7   -> cols c0..c0+7
    const int r0 = rg * 6;
    const int c0 = cg * 8;

    float acc[6][8];
    #pragma unroll
    for (int rr = 0; rr < 6; ++rr)
        #pragma unroll
        for (int j = 0; j < 8; ++j) acc[rr][j] = bias[c0 + j];

    #pragma unroll
    for (int k = 0; k < 3; ++k) {
        const float* Ak = (k == 0) ? A0 : (k == 1) ? A1 : A2;
        const float* Wk = Wsm + k * 4096;
        #pragma unroll 4
        for (int i = 0; i < DD; ++i) {
            float w[8];
            #pragma unroll
            for (int j = 0; j < 8; ++j) w[j] = Wk[i * DD + c0 + j];
            #pragma unroll
            for (int rr = 0; rr < 6; ++rr) {
                const float a = Ak[(r0 + rr) * APAD + i];
                #pragma unroll
                for (int j = 0; j < 8; ++j)
                    acc[rr][j] = fmaf(a, w[j], acc[rr][j]);
            }
        }
    }

    #pragma unroll
    for (int rr = 0; rr < 6; ++rr) {
        const int r = r0 + rr;
        const int b = r / TT, t = r % TT;
        float* op = out + ((size_t)(b * NN + n) * TT + t) * DD + c0;
        *(float4*)(op)     = make_float4(acc[rr][0], acc[rr][1], acc[rr][2], acc[rr][3]);
        *(float4*)(op + 4) = make_float4(acc[rr][4], acc[rr][5], acc[rr][6], acc[rr][7]);
    }
}

// ---------------- launcher -------------------------------------------------
extern "C" void kernel_launch(void* const* d_in, const int* in_sizes, int n_in,
                              void* d_out, int out_size) {
    const float* x   = (const float*)d_in[0];   // [B,N,T,D]
    const float* emb = (const float*)d_in[1];   // [N,E]
    const float* wp  = (const float*)d_in[2];   // [E,K,D,D]
    const float* bp  = (const float*)d_in[3];   // [E,D]
    float* out = (float*)d_out;                 // [B,N,T,D]

    __nv_bfloat16 *Shi, *Slo, *Bhi, *Blo;
    float *X, *Y1, *Y2;
    cudaGetSymbolAddress((void**)&Shi, g_Shi);
    cudaGetSymbolAddress((void**)&Slo, g_Slo);
    cudaGetSymbolAddress((void**)&X,   g_X);
    cudaGetSymbolAddress((void**)&Bhi, g_Bhi);
    cudaGetSymbolAddress((void**)&Blo, g_Blo);
    cudaGetSymbolAddress((void**)&Y1,  g_Y1);
    cudaGetSymbolAddress((void**)&Y2,  g_Y2);

    cudaFuncSetAttribute(mma_gemm_kernel,
                         cudaFuncAttributeMaxDynamicSharedMemorySize,
                         GEMM_SMEM_BYTES);
    cudaFuncSetAttribute(final_kernel,
                         cudaFuncAttributeMaxDynamicSharedMemorySize,
                         FINAL_SMEM_BYTES);

    support_kernel<<<NN, 256>>>(emb, Shi, Slo);

    const int total4 = NN * (COLS / 4);
    reshape_kernel<<<(total4 + 255) / 256, 256>>>(x, X);

    dim3 tgrid(COLS / 32, NN / 32);
    dim3 ggrid(COLS / 128, NN / 128);    // x over N (96) fastest, y over M (16)

    tsplit_kernel<<<tgrid, 256>>>(X, Bhi, Blo);                       // X^T split
    mma_gemm_kernel<<<ggrid, 256, GEMM_SMEM_BYTES>>>(Shi, Slo, Bhi, Blo, Y1);
    tsplit_kernel<<<tgrid, 256>>>(Y1, Bhi, Blo);                      // Y1^T split
    mma_gemm_kernel<<<ggrid, 256, GEMM_SMEM_BYTES>>>(Shi, Slo, Bhi, Blo, Y2);

    final_kernel<<<NN, 256, FINAL_SMEM_BYTES>>>(emb, wp, bp, X, Y1, Y2, out);
}

// round 11
// speedup vs baseline: 4.6586x; 1.0620x over previous
#include <cuda_runtime.h>
#include <cuda_bf16.h>
#include <cstdint>

#define BATCH 16
#define NN    2048
#define TT    12
#define DD    64
#define EE    16
#define BTT   192            // BATCH * TT
#define COLS  12288          // BTT * DD

// ---------------- scratch (static device globals) --------------------------
__device__ __nv_bfloat16 g_Shi[(size_t)NN * NN];        // S hi  [N,N]
__device__ __nv_bfloat16 g_Slo[(size_t)NN * NN];        // S lo
__device__ float         g_X  [(size_t)NN * COLS];      // xr as [N, BT*D]
__device__ __nv_bfloat16 g_Bhi[(size_t)COLS * NN];      // transposed operand hi
__device__ __nv_bfloat16 g_Blo[(size_t)COLS * NN];      // transposed operand lo
__device__ float         g_Y1 [(size_t)NN * COLS];      // S @ X
__device__ float         g_Y2 [(size_t)NN * COLS];      // S @ Y1

// ==================== helpers (baseline PTX only, safe on sm_103) ==========
__device__ __forceinline__ uint32_t smem_to_u32(const void* p) {
    uint32_t a;
    asm("{ .reg .u64 t; cvta.to.shared.u64 t, %1; cvt.u32.u64 %0, t; }"
        : "=r"(a) : "l"(p));
    return a;
}

// SW128 swizzle for 128-byte rows: bits[6:4] ^= bits[9:7]  (conflict-free)
__device__ __forceinline__ uint32_t swz128(uint32_t o) {
    return o ^ ((o >> 3) & 0x70u);
}

__device__ __forceinline__ void cp_async16(uint32_t saddr, const void* gaddr) {
    asm volatile("cp.async.cg.shared.global [%0], [%1], 16;"
                 :: "r"(saddr), "l"(gaddr));
}
#define CP_COMMIT() asm volatile("cp.async.commit_group;")
#define CP_WAIT1()  asm volatile("cp.async.wait_group 1;")

__device__ __forceinline__ void ldmx4(uint32_t r[4], uint32_t addr) {
    asm volatile("ldmatrix.sync.aligned.m8n8.x4.shared.b16 {%0,%1,%2,%3}, [%4];"
                 : "=r"(r[0]), "=r"(r[1]), "=r"(r[2]), "=r"(r[3]) : "r"(addr));
}

__device__ __forceinline__ void mma_bf16(float4& d, const uint32_t a[4],
                                         const uint32_t b[2]) {
    asm volatile(
        "mma.sync.aligned.m16n8k16.row.col.f32.bf16.bf16.f32 "
        "{%0,%1,%2,%3}, {%4,%5,%6,%7}, {%8,%9}, {%0,%1,%2,%3};"
        : "+f"(d.x), "+f"(d.y), "+f"(d.z), "+f"(d.w)
        : "r"(a[0]), "r"(a[1]), "r"(a[2]), "r"(a[3]), "r"(b[0]), "r"(b[1]));
}

__device__ __forceinline__ uint32_t pack_bf16(float x, float y) {
    __nv_bfloat162 t = __floats2bfloat162_rn(x, y);   // x -> low, y -> high
    return *(uint32_t*)&t;
}

// ---------------- kernel 1: supports = softmax(relu(E E^T)) -> hi/lo bf16 --
__global__ __launch_bounds__(256)
void support_kernel(const float* __restrict__ emb,
                    __nv_bfloat16* __restrict__ Shi,
                    __nv_bfloat16* __restrict__ Slo) {
    const int n   = blockIdx.x;
    const int tid = threadIdx.x;

    const float4* er = (const float4*)(emb + n * EE);
    const float4 e0 = er[0], e1 = er[1], e2 = er[2], e3 = er[3];

    float v[8];
    float mx = -1e30f;
    #pragma unroll
    for (int jj = 0; jj < 8; ++jj) {
        const int m = jj * 256 + tid;
        const float4* fm = (const float4*)(emb + m * EE);
        const float4 f0 = fm[0], f1 = fm[1], f2 = fm[2], f3 = fm[3];
        float d = e0.x*f0.x + e0.y*f0.y + e0.z*f0.z + e0.w*f0.w
                + e1.x*f1.x + e1.y*f1.y + e1.z*f1.z + e1.w*f1.w
                + e2.x*f2.x + e2.y*f2.y + e2.z*f2.z + e2.w*f2.w
                + e3.x*f3.x + e3.y*f3.y + e3.z*f3.z + e3.w*f3.w;
        d = fmaxf(d, 0.0f);
        v[jj] = d;
        mx = fmaxf(mx, d);
    }

    __shared__ float red[256];
    red[tid] = mx;
    __syncthreads();
    for (int s = 128; s > 0; s >>= 1) {
        if (tid < s) red[tid] = fmaxf(red[tid], red[tid + s]);
        __syncthreads();
    }
    mx = red[0];
    __syncthreads();

    float sum = 0.0f;
    #pragma unroll
    for (int jj = 0; jj < 8; ++jj) {
        v[jj] = expf(v[jj] - mx);
        sum += v[jj];
    }
    red[tid] = sum;
    __syncthreads();
    for (int s = 128; s > 0; s >>= 1) {
        if (tid < s) red[tid] += red[tid + s];
        __syncthreads();
    }
    const float inv = 1.0f / red[0];

    #pragma unroll
    for (int jj = 0; jj < 8; ++jj) {
        const float val = v[jj] * inv;
        const __nv_bfloat16 h = __float2bfloat16(val);
        const size_t o = (size_t)n * NN + jj * 256 + tid;
        Shi[o] = h;
        Slo[o] = __float2bfloat16(val - __bfloat162float(h));
    }
}

// ---------------- kernel 2: fused reshape + transpose + split --------------
// reads x[B,N,T,D]; writes X[N,COLS] fp32 AND Bhi/Blo [COLS,NN] bf16.
__global__ __launch_bounds__(256)
void tsplitA_kernel(const float* __restrict__ x, float* __restrict__ X,
                    __nv_bfloat16* __restrict__ hi,
                    __nv_bfloat16* __restrict__ lo) {
    __shared__ float tile[32][33];
    const int tx = threadIdx.x & 31;
    const int ty = threadIdx.x >> 5;     // 0..7
    const int c0 = blockIdx.x * 32;      // over COLS
    const int r0 = blockIdx.y * 32;      // over NN
    const int c  = c0 + tx;
    const int bt = c >> 6;
    const int d  = c & 63;
    const int b  = bt / TT;
    const int t  = bt % TT;
    #pragma unroll
    for (int j = 0; j < 4; ++j) {
        const int n = r0 + ty + j * 8;
        const float v = x[((size_t)(b * NN + n) * TT + t) * DD + d];
        X[(size_t)n * COLS + c] = v;
        tile[ty + j * 8][tx] = v;
    }
    __syncthreads();
    #pragma unroll
    for (int j = 0; j < 4; ++j) {
        const int cc = ty + j * 8;
        const float v = tile[tx][cc];
        const __nv_bfloat16 h = __float2bfloat16(v);
        const size_t o = (size_t)(c0 + cc) * NN + r0 + tx;
        hi[o] = h;
        lo[o] = __float2bfloat16(v - __bfloat162float(h));
    }
}

// ---------------- kernel 3: transpose + hi/lo split (Y1 pass) --------------
__global__ __launch_bounds__(256)
void tsplit_kernel(const float* __restrict__ in,
                   __nv_bfloat16* __restrict__ hi,
                   __nv_bfloat16* __restrict__ lo) {
    __shared__ float tile[32][33];
    const int tx = threadIdx.x & 31;
    const int ty = threadIdx.x >> 5;
    const int c0 = blockIdx.x * 32;
    const int r0 = blockIdx.y * 32;
    #pragma unroll
    for (int j = 0; j < 4; ++j)
        tile[ty + j * 8][tx] = in[(size_t)(r0 + ty + j * 8) * COLS + c0 + tx];
    __syncthreads();
    #pragma unroll
    for (int j = 0; j < 4; ++j) {
        const int c = ty + j * 8;
        const float v = tile[tx][c];
        const __nv_bfloat16 h = __float2bfloat16(v);
        const size_t o = (size_t)(c0 + c) * NN + r0 + tx;
        hi[o] = h;
        lo[o] = __float2bfloat16(v - __bfloat162float(h));
    }
}

// ---------------- kernel 4/5: mma.sync GEMM  C = A * B^T -------------------
#define STG_BYTES 32768            // A 16KB + B 16KB
#define OFF_A 0
#define OFF_B 16384
#define GEMM_SMEM_BYTES (3 * STG_BYTES)   // 98304

__device__ __forceinline__ void load_stage(
    uint32_t sbase, int buf,
    const __nv_bfloat16* __restrict__ Ah, const __nv_bfloat16* __restrict__ Al,
    const __nv_bfloat16* __restrict__ Bh, const __nv_bfloat16* __restrict__ Bl,
    int m0, int n0, int k0, int tid)
{
    const int row = tid >> 3;            // 0..31
    const int ch  = tid & 7;             // 16B chunk within 128B row
    const int kc  = (ch & 3) * 8;        // k-element offset within 32
    const bool lo = (ch >= 4);
    const uint32_t st = sbase + buf * STG_BYTES;
    const __nv_bfloat16* Asrc = lo ? Al : Ah;
    const __nv_bfloat16* Bsrc = lo ? Bl : Bh;
    #pragma unroll
    for (int h = 0; h < 4; ++h) {
        const int r = row + h * 32;      // 0..127
        const uint32_t so = swz128((uint32_t)(r * 128 + ch * 16));
        cp_async16(st + OFF_A + so, Asrc + (size_t)(m0 + r) * NN + k0 + kc);
        cp_async16(st + OFF_B + so, Bsrc + (size_t)(n0 + r) * NN + k0 + kc);
    }
}

__global__ __launch_bounds__(256)
void mma_gemm_kernel(const __nv_bfloat16* __restrict__ Ah,
                     const __nv_bfloat16* __restrict__ Al,
                     const __nv_bfloat16* __restrict__ Bh,
                     const __nv_bfloat16* __restrict__ Bl,
                     float* __restrict__ C) {
    extern __shared__ __align__(1024) char smem[];
    const uint32_t sbase = smem_to_u32(smem);
    const int tid  = threadIdx.x;
    const int lane = tid & 31;
    const int wid  = tid >> 5;
    const int wm   = wid & 1;            // 2 warps over M
    const int wn   = wid >> 1;           // 4 warps over N
    const int n0   = blockIdx.x * 128;   // grid.x over COLS (96)
    const int m0   = blockIdx.y * 128;   // grid.y over M (16)

    const int lr_a = lane & 15;
    const int kh_a = lane >> 4;
    const int lr_b = (lane & 7) | ((lane & 16) >> 1);
    const int kh_b = (lane >> 3) & 1;

    float4 acc[4][4];
    #pragma unroll
    for (int i = 0; i < 4; ++i)
        #pragma unroll
        for (int j = 0; j < 4; ++j) acc[i][j] = make_float4(0.f, 0.f, 0.f, 0.f);

    // prologue: 2 stages in flight
    #pragma unroll
    for (int s = 0; s < 2; ++s) {
        load_stage(sbase, s, Ah, Al, Bh, Bl, m0, n0, s * 32, tid);
        CP_COMMIT();
    }

    const int NITER = NN / 32;           // 64
    int buf = 0, ldbuf = 2;
    for (int it = 0; it < NITER; ++it) {
        CP_WAIT1();                      // stage `it` resident
        __syncthreads();                 // everyone done with iter it-1 + data visible

        if (it + 2 < NITER)
            load_stage(sbase, ldbuf, Ah, Al, Bh, Bl, m0, n0, (it + 2) * 32, tid);
        CP_COMMIT();

        const uint32_t st = sbase + buf * STG_BYTES;
        #pragma unroll
        for (int ks = 0; ks < 2; ++ks) {
            uint32_t ah[4][4], al[4][4], bh[4][2], bl[4][2];
            #pragma unroll
            for (int mi = 0; mi < 4; ++mi) {
                const int r = wm * 64 + mi * 16 + lr_a;
                const uint32_t base = (uint32_t)(r * 128 + ks * 32 + kh_a * 16);
                ldmx4(ah[mi], st + OFF_A + swz128(base));
                ldmx4(al[mi], st + OFF_A + swz128(base + 64u));
            }
            #pragma unroll
            for (int nt = 0; nt < 2; ++nt) {
                const int r = wn * 32 + nt * 16 + lr_b;
                const uint32_t base = (uint32_t)(r * 128 + ks * 32 + kh_b * 16);
                uint32_t t[4];
                ldmx4(t, st + OFF_B + swz128(base));
                bh[nt * 2][0] = t[0]; bh[nt * 2][1] = t[1];
                bh[nt * 2 + 1][0] = t[2]; bh[nt * 2 + 1][1] = t[3];
                ldmx4(t, st + OFF_B + swz128(base + 64u));
                bl[nt * 2][0] = t[0]; bl[nt * 2][1] = t[1];
                bl[nt * 2 + 1][0] = t[2]; bl[nt * 2 + 1][1] = t[3];
            }
            #pragma unroll
            for (int mi = 0; mi < 4; ++mi)
                #pragma unroll
                for (int nj = 0; nj < 4; ++nj)
                    mma_bf16(acc[mi][nj], ah[mi], bh[nj]);
            #pragma unroll
            for (int mi = 0; mi < 4; ++mi)
                #pragma unroll
                for (int nj = 0; nj < 4; ++nj)
                    mma_bf16(acc[mi][nj], ah[mi], bl[nj]);
            #pragma unroll
            for (int mi = 0; mi < 4; ++mi)
                #pragma unroll
                for (int nj = 0; nj < 4; ++nj)
                    mma_bf16(acc[mi][nj], al[mi], bh[nj]);
        }

        buf   = (buf   + 1 == 3) ? 0 : buf   + 1;
        ldbuf = (ldbuf + 1 == 3) ? 0 : ldbuf + 1;
    }

    // epilogue
    const int g  = lane >> 2;
    const int id = lane & 3;
    #pragma unroll
    for (int mi = 0; mi < 4; ++mi) {
        const int row = m0 + wm * 64 + mi * 16 + g;
        #pragma unroll
        for (int nj = 0; nj < 4; ++nj) {
            const int col = n0 + wn * 32 + nj * 8 + id * 2;
            float2* p0 = (float2*)(C + (size_t)row * COLS + col);
            float2* p1 = (float2*)(C + (size_t)(row + 8) * COLS + col);
            *p0 = make_float2(acc[mi][nj].x, acc[mi][nj].y);
            *p1 = make_float2(acc[mi][nj].z, acc[mi][nj].w);
        }
    }
}

// ---------------- kernel 6: tensorized per-node hypernet + grouped GEMM ----
// Smem map (bytes):
//   W panels : k*16384 + {hi:0, lo:8192} + swz128(o*128 + i*2)   [0, 49152)
//   A panels : 49152 + {hi:0, lo:24576} + swz128(r*128 + i*2)    [49152, 98304)
//   (W-prep scratch [64][65] fp32 = 16640B overlaps the A area)
//   bias     : 98304 (64 fp32)   En: 98560 (16 fp32)
#define FA_OFF    49152
#define FALO_OFF  24576
#define FBIAS_OFF 98304
#define FEN_OFF   98560
#define FINAL_SMEM_BYTES 98624

__global__ __launch_bounds__(256, 2)
void final_mma_kernel(const float* __restrict__ emb, const float* __restrict__ wp,
                      const float* __restrict__ bp,  const float* __restrict__ X,
                      const float* __restrict__ Y1,  const float* __restrict__ Y2,
                      float* __restrict__ out) {
    extern __shared__ __align__(1024) char fsm[];
    const uint32_t sb = smem_to_u32(fsm);
    float* scratch = (float*)(fsm + FA_OFF);          // 64x65 fp32, pre-A-staging
    float* biasS   = (float*)(fsm + FBIAS_OFF);
    float* EnS     = (float*)(fsm + FEN_OFF);

    const int n    = blockIdx.x;
    const int tid  = threadIdx.x;
    const int lane = tid & 31;
    const int wid  = tid >> 5;
    const int wm   = wid & 3;            // 4 warps over M (48 rows each)
    const int wn   = wid >> 2;           // 2 warps over N (32 cols each)

    if (tid < EE) EnS[tid] = emb[n * EE + tid];
    __syncthreads();
    float En[EE];
    #pragma unroll
    for (int e = 0; e < EE; ++e) En[e] = EnS[e];

    if (tid < DD) {
        float s = 0.0f;
        #pragma unroll
        for (int e = 0; e < EE; ++e) s = fmaf(En[e], bp[e * DD + tid], s);
        biasS[tid] = s;
    }

    // ---- hypernet weights -> SW128 panels (scratch-transposed) ----
    #pragma unroll
    for (int k = 0; k < 3; ++k) {
        // phase 1: coalesced j-natural compute into padded scratch [i][o]
        for (int idx = tid; idx < 4096; idx += 256) {
            const int i = idx >> 6, o = idx & 63;
            float s = 0.0f;
            #pragma unroll
            for (int e = 0; e < EE; ++e)
                s = fmaf(En[e], wp[e * 12288 + k * 4096 + idx], s);
            scratch[i * 65 + o] = s;
        }
        __syncthreads();
        // phase 2: transpose to panel [o][i], split hi/lo, conflict-free writes
        for (int idx = tid; idx < 2048; idx += 256) {
            const int o = idx >> 5, i0 = (idx & 31) * 2;
            const float f0 = scratch[i0 * 65 + o];
            const float f1 = scratch[(i0 + 1) * 65 + o];
            const __nv_bfloat16 h0 = __float2bfloat16(f0);
            const __nv_bfloat16 h1 = __float2bfloat16(f1);
            const uint32_t off = swz128((uint32_t)(o * 128 + i0 * 2));
            *(uint32_t*)(fsm + k * 16384 + off) =
                pack_bf16(__bfloat162float(h0), __bfloat162float(h1));
            *(uint32_t*)(fsm + k * 16384 + 8192 + off) =
                pack_bf16(f0 - __bfloat162float(h0), f1 - __bfloat162float(h1));
        }
        __syncthreads();
    }

    const int lr_a = lane & 15;
    const int kh_a = lane >> 4;
    const int lr_b = (lane & 7) | ((lane & 16) >> 1);
    const int kh_b = (lane >> 3) & 1;

    float4 acc[3][4];
    #pragma unroll
    for (int i = 0; i < 3; ++i)
        #pragma unroll
        for (int j = 0; j < 4; ++j) acc[i][j] = make_float4(0.f, 0.f, 0.f, 0.f);

    const float* Xr  = X  + (size_t)n * COLS;
    const float* Y1r = Y1 + (size_t)n * COLS;
    const float* Y2r = Y2 + (size_t)n * COLS;

    #pragma unroll
    for (int kc = 0; kc < 3; ++kc) {
        // stage A_kc [192][64] -> hi/lo panels
        for (int idx = tid; idx < 6144; idx += 256) {
            const int r = idx >> 5, i0 = (idx & 31) * 2;
            float2 v;
            if (kc == 0)      v = *(const float2*)(Xr  + r * 64 + i0);
            else if (kc == 1) v = *(const float2*)(Y1r + r * 64 + i0);
            else {
                const float2 a = *(const float2*)(Y2r + r * 64 + i0);
                const float2 b = *(const float2*)(Xr  + r * 64 + i0);
                v.x = 2.0f * a.x - b.x; v.y = 2.0f * a.y - b.y;
            }
            const __nv_bfloat16 h0 = __float2bfloat16(v.x);
            const __nv_bfloat16 h1 = __float2bfloat16(v.y);
            const uint32_t off = swz128((uint32_t)(r * 128 + i0 * 2));
            *(uint32_t*)(fsm + FA_OFF + off) =
                pack_bf16(__bfloat162float(h0), __bfloat162float(h1));
            *(uint32_t*)(fsm + FA_OFF + FALO_OFF + off) =
                pack_bf16(v.x - __bfloat162float(h0), v.y - __bfloat162float(h1));
        }
        __syncthreads();

        const uint32_t whB = sb + kc * 16384;
        const uint32_t wlB = whB + 8192;
        const uint32_t ahB = sb + FA_OFF;
        const uint32_t alB = ahB + FALO_OFF;
        #pragma unroll
        for (int ks = 0; ks < 4; ++ks) {
            uint32_t ah[3][4], al[3][4], bh[4][2], bl[4][2];
            #pragma unroll
            for (int mi = 0; mi < 3; ++mi) {
                const int r = wm * 48 + mi * 16 + lr_a;
                const uint32_t base = (uint32_t)(r * 128 + ks * 32 + kh_a * 16);
                ldmx4(ah[mi], ahB + swz128(base));
                ldmx4(al[mi], alB + swz128(base));
            }
            #pragma unroll
            for (int np = 0; np < 2; ++np) {
                const int o = wn * 32 + np * 16 + lr_b;
                const uint32_t base = (uint32_t)(o * 128 + ks * 32 + kh_b * 16);
                uint32_t t[4];
                ldmx4(t, whB + swz128(base));
                bh[np * 2][0] = t[0]; bh[np * 2][1] = t[1];
                bh[np * 2 + 1][0] = t[2]; bh[np * 2 + 1][1] = t[3];
                ldmx4(t, wlB + swz128(base));
                bl[np * 2][0] = t[0]; bl[np * 2][1] = t[1];
                bl[np * 2 + 1][0] = t[2]; bl[np * 2 + 1][1] = t[3];
            }
            #pragma unroll
            for (int mi = 0; mi < 3; ++mi)
                #pragma unroll
                for (int nj = 0; nj < 4; ++nj)
                    mma_bf16(acc[mi][nj], ah[mi], bh[nj]);
            #pragma unroll
            for (int mi = 0; mi < 3; ++mi)
                #pragma unroll
                for (int nj = 0; nj < 4; ++nj)
                    mma_bf16(acc[mi][nj], ah[mi], bl[nj]);
            #pragma unroll
            for (int mi = 0; mi < 3; ++mi)
                #pragma unroll
                for (int nj = 0; nj < 4; ++nj)
                    mma_bf16(acc[mi][nj], al[mi], bh[nj]);
        }
        __syncthreads();   // protect A panels before next kc restage
    }

    // epilogue: bias + scatter to out[B,N,T,D]
    const int g  = lane >> 2;
    const int id = lane & 3;
    #pragma unroll
    for (int mi = 0; mi < 3; ++mi) {
        const int r = wm * 48 + mi * 16 + g;
        #pragma unroll
        for (int nj = 0; nj < 4; ++nj) {
            const int o = wn * 32 + nj * 8 + id * 2;
            const float b0 = biasS[o], b1 = biasS[o + 1];
            {
                const int b = r / TT, t = r % TT;
                float2* p = (float2*)(out + ((size_t)(b * NN + n) * TT + t) * DD + o);
                *p = make_float2(acc[mi][nj].x + b0, acc[mi][nj].y + b1);
            }
            {
                const int r2 = r + 8;
                const int b = r2 / TT, t = r2 % TT;
                float2* p = (float2*)(out + ((size_t)(b * NN + n) * TT + t) * DD + o);
                *p = make_float2(acc[mi][nj].z + b0, acc[mi][nj].w + b1);
            }
        }
    }
}

// ---------------- launcher -------------------------------------------------
extern "C" void kernel_launch(void* const* d_in, const int* in_sizes, int n_in,
                              void* d_out, int out_size) {
    const float* x   = (const float*)d_in[0];   // [B,N,T,D]
    const float* emb = (const float*)d_in[1];   // [N,E]
    const float* wp  = (const float*)d_in[2];   // [E,K,D,D]
    const float* bp  = (const float*)d_in[3];   // [E,D]
    float* out = (float*)d_out;                 // [B,N,T,D]

    __nv_bfloat16 *Shi, *Slo, *Bhi, *Blo;
    float *X, *Y1, *Y2;
    cudaGetSymbolAddress((void**)&Shi, g_Shi);
    cudaGetSymbolAddress((void**)&Slo, g_Slo);
    cudaGetSymbolAddress((void**)&X,   g_X);
    cudaGetSymbolAddress((void**)&Bhi, g_Bhi);
    cudaGetSymbolAddress((void**)&Blo, g_Blo);
    cudaGetSymbolAddress((void**)&Y1,  g_Y1);
    cudaGetSymbolAddress((void**)&Y2,  g_Y2);

    cudaFuncSetAttribute(mma_gemm_kernel,
                         cudaFuncAttributeMaxDynamicSharedMemorySize,
                         GEMM_SMEM_BYTES);
    cudaFuncSetAttribute(final_mma_kernel,
                         cudaFuncAttributeMaxDynamicSharedMemorySize,
                         FINAL_SMEM_BYTES);

    support_kernel<<<NN, 256>>>(emb, Shi, Slo);

    dim3 tgrid(COLS / 32, NN / 32);
    dim3 ggrid(COLS / 128, NN / 128);    // x over N (96) fastest, y over M (16)

    tsplitA_kernel<<<tgrid, 256>>>(x, X, Bhi, Blo);   // fused reshape+transpose+split
    mma_gemm_kernel<<<ggrid, 256, GEMM_SMEM_BYTES>>>(Shi, Slo, Bhi, Blo, Y1);
    tsplit_kernel<<<tgrid, 256>>>(Y1, Bhi, Blo);      // Y1^T split
    mma_gemm_kernel<<<ggrid, 256, GEMM_SMEM_BYTES>>>(Shi, Slo, Bhi, Blo, Y2);

    final_mma_kernel<<<NN, 256, FINAL_SMEM_BYTES>>>(emb, wp, bp, X, Y1, Y2, out);
}

// round 16
// speedup vs baseline: 4.9605x; 1.0648x over previous
#include <cuda_runtime.h>
#include <cuda_bf16.h>
#include <cstdint>

#define BATCH 16
#define NN    2048
#define TT    12
#define DD    64
#define EE    16
#define BTT   192            // BATCH * TT
#define COLS  12288          // BTT * DD

// ---------------- scratch (static device globals) --------------------------
__device__ __nv_bfloat16 g_Shi[(size_t)NN * NN];        // S hi  [N,N]
__device__ __nv_bfloat16 g_Slo[(size_t)NN * NN];        // S lo
__device__ float         g_X  [(size_t)NN * COLS];      // xr as [N, BT*D]
__device__ __nv_bfloat16 g_Bhi[(size_t)COLS * NN];      // X^T split hi
__device__ __nv_bfloat16 g_Blo[(size_t)COLS * NN];      // X^T split lo
__device__ __nv_bfloat16 g_B2hi[(size_t)COLS * NN];     // Y1^T split hi (GEMM1 out)
__device__ __nv_bfloat16 g_B2lo[(size_t)COLS * NN];     // Y1^T split lo
__device__ float         g_Y1 [(size_t)NN * COLS];      // S @ X
__device__ float         g_Y2 [(size_t)NN * COLS];      // S @ Y1
__device__ char          g_W  [(size_t)NN * 3 * 16384]; // per-node W panels (swizzled hi/lo bf16)

// ==================== helpers (baseline PTX only, safe on sm_103) ==========
__device__ __forceinline__ uint32_t smem_to_u32(const void* p) {
    uint32_t a;
    asm("{ .reg .u64 t; cvta.to.shared.u64 t, %1; cvt.u32.u64 %0, t; }"
        : "=r"(a) : "l"(p));
    return a;
}

// SW128 swizzle for 128-byte rows: bits[6:4] ^= bits[9:7]  (conflict-free)
__device__ __forceinline__ uint32_t swz128(uint32_t o) {
    return o ^ ((o >> 3) & 0x70u);
}

__device__ __forceinline__ void cp_async16(uint32_t saddr, const void* gaddr) {
    asm volatile("cp.async.cg.shared.global [%0], [%1], 16;"
                 :: "r"(saddr), "l"(gaddr));
}
#define CP_COMMIT() asm volatile("cp.async.commit_group;")
#define CP_WAIT1()  asm volatile("cp.async.wait_group 1;")
#define CP_WAIT0()  asm volatile("cp.async.wait_group 0;")

__device__ __forceinline__ void ldmx4(uint32_t r[4], uint32_t addr) {
    asm volatile("ldmatrix.sync.aligned.m8n8.x4.shared.b16 {%0,%1,%2,%3}, [%4];"
                 : "=r"(r[0]), "=r"(r[1]), "=r"(r[2]), "=r"(r[3]) : "r"(addr));
}

__device__ __forceinline__ void mma_bf16(float4& d, const uint32_t a[4],
                                         const uint32_t b[2]) {
    asm volatile(
        "mma.sync.aligned.m16n8k16.row.col.f32.bf16.bf16.f32 "
        "{%0,%1,%2,%3}, {%4,%5,%6,%7}, {%8,%9}, {%0,%1,%2,%3};"
        : "+f"(d.x), "+f"(d.y), "+f"(d.z), "+f"(d.w)
        : "r"(a[0]), "r"(a[1]), "r"(a[2]), "r"(a[3]), "r"(b[0]), "r"(b[1]));
}

__device__ __forceinline__ uint32_t pack_bf16(float x, float y) {
    __nv_bfloat162 t = __floats2bfloat162_rn(x, y);   // x -> low, y -> high
    return *(uint32_t*)&t;
}

// ---------------- kernel 1: supports = softmax(relu(E E^T)) -> hi/lo bf16 --
__global__ __launch_bounds__(256)
void support_kernel(const float* __restrict__ emb,
                    __nv_bfloat16* __restrict__ Shi,
                    __nv_bfloat16* __restrict__ Slo) {
    const int n   = blockIdx.x;
    const int tid = threadIdx.x;

    const float4* er = (const float4*)(emb + n * EE);
    const float4 e0 = er[0], e1 = er[1], e2 = er[2], e3 = er[3];

    float v[8];
    float mx = -1e30f;
    #pragma unroll
    for (int jj = 0; jj < 8; ++jj) {
        const int m = jj * 256 + tid;
        const float4* fm = (const float4*)(emb + m * EE);
        const float4 f0 = fm[0], f1 = fm[1], f2 = fm[2], f3 = fm[3];
        float d = e0.x*f0.x + e0.y*f0.y + e0.z*f0.z + e0.w*f0.w
                + e1.x*f1.x + e1.y*f1.y + e1.z*f1.z + e1.w*f1.w
                + e2.x*f2.x + e2.y*f2.y + e2.z*f2.z + e2.w*f2.w
                + e3.x*f3.x + e3.y*f3.y + e3.z*f3.z + e3.w*f3.w;
        d = fmaxf(d, 0.0f);
        v[jj] = d;
        mx = fmaxf(mx, d);
    }

    __shared__ float red[256];
    red[tid] = mx;
    __syncthreads();
    for (int s = 128; s > 0; s >>= 1) {
        if (tid < s) red[tid] = fmaxf(red[tid], red[tid + s]);
        __syncthreads();
    }
    mx = red[0];
    __syncthreads();

    float sum = 0.0f;
    #pragma unroll
    for (int jj = 0; jj < 8; ++jj) {
        v[jj] = expf(v[jj] - mx);
        sum += v[jj];
    }
    red[tid] = sum;
    __syncthreads();
    for (int s = 128; s > 0; s >>= 1) {
        if (tid < s) red[tid] += red[tid + s];
        __syncthreads();
    }
    const float inv = 1.0f / red[0];

    #pragma unroll
    for (int jj = 0; jj < 8; ++jj) {
        const float val = v[jj] * inv;
        const __nv_bfloat16 h = __float2bfloat16(val);
        const size_t o = (size_t)n * NN + jj * 256 + tid;
        Shi[o] = h;
        Slo[o] = __float2bfloat16(val - __bfloat162float(h));
    }
}

// ---------------- kernel 2: fused reshape + transpose + split --------------
__global__ __launch_bounds__(256)
void tsplitA_kernel(const float* __restrict__ x, float* __restrict__ X,
                    __nv_bfloat16* __restrict__ hi,
                    __nv_bfloat16* __restrict__ lo) {
    __shared__ float tile[32][33];
    const int tx = threadIdx.x & 31;
    const int ty = threadIdx.x >> 5;     // 0..7
    const int c0 = blockIdx.x * 32;      // over COLS
    const int r0 = blockIdx.y * 32;      // over NN
    const int c  = c0 + tx;
    const int bt = c >> 6;
    const int d  = c & 63;
    const int b  = bt / TT;
    const int t  = bt % TT;
    #pragma unroll
    for (int j = 0; j < 4; ++j) {
        const int n = r0 + ty + j * 8;
        const float v = x[((size_t)(b * NN + n) * TT + t) * DD + d];
        X[(size_t)n * COLS + c] = v;
        tile[ty + j * 8][tx] = v;
    }
    __syncthreads();
    #pragma unroll
    for (int j = 0; j < 4; ++j) {
        const int cc = ty + j * 8;
        const float v = tile[tx][cc];
        const __nv_bfloat16 h = __float2bfloat16(v);
        const size_t o = (size_t)(c0 + cc) * NN + r0 + tx;
        hi[o] = h;
        lo[o] = __float2bfloat16(v - __bfloat162float(h));
    }
}

// ---------------- kernel 3: hypernet weight precompute ---------------------
// W[n,k] = sum_e emb[n,e] * wp[e,k,:,:]  -> swizzled hi/lo bf16 panels [o][i]
__global__ __launch_bounds__(256)
void wprep_kernel(const float* __restrict__ emb, const float* __restrict__ wp,
                  char* __restrict__ Wg) {
    __shared__ float wpS[16 * 512];      // [e][i(8)][o(64)]  32KB
    __shared__ float embS[16][16];
    const int k   = blockIdx.x;
    const int g   = blockIdx.y;
    const int tid = threadIdx.x;

    embS[tid >> 4][tid & 15] = emb[(g * 16 + (tid >> 4)) * EE + (tid & 15)];

    for (int ic = 0; ic < 8; ++ic) {     // 8 chunks of 8 i-rows
        __syncthreads();
        #pragma unroll
        for (int q = 0; q < 32; ++q) {
            const int idx = tid + q * 256;        // 0..8191
            const int e = idx >> 9;
            const int rest = idx & 511;           // i*64 + o
            wpS[idx] = wp[e * 12288 + k * 4096 + ic * 512 + rest];
        }
        __syncthreads();
        #pragma unroll
        for (int q = 0; q < 4; ++q) {
            const int item = tid + q * 256;       // 0..1023
            const int nl = item >> 6;
            const int o  = item & 63;
            float s[8];
            #pragma unroll
            for (int i = 0; i < 8; ++i) s[i] = 0.0f;
            #pragma unroll
            for (int e = 0; e < EE; ++e) {
                const float ev = embS[nl][e];
                #pragma unroll
                for (int i = 0; i < 8; ++i)
                    s[i] = fmaf(ev, wpS[e * 512 + i * 64 + o], s[i]);
            }
            uint32_t hi[4], lo[4];
            #pragma unroll
            for (int p = 0; p < 4; ++p) {
                const float f0 = s[2 * p], f1 = s[2 * p + 1];
                const __nv_bfloat16 h0 = __float2bfloat16(f0);
                const __nv_bfloat16 h1 = __float2bfloat16(f1);
                hi[p] = pack_bf16(__bfloat162float(h0), __bfloat162float(h1));
                lo[p] = pack_bf16(f0 - __bfloat162float(h0),
                                  f1 - __bfloat162float(h1));
            }
            char* base = Wg + ((size_t)(g * 16 + nl) * 3 + k) * 16384;
            const uint32_t off = swz128((uint32_t)(o * 128 + ic * 16));
            *(uint4*)(base + off)        = make_uint4(hi[0], hi[1], hi[2], hi[3]);
            *(uint4*)(base + 8192 + off) = make_uint4(lo[0], lo[1], lo[2], lo[3]);
        }
    }
}

// ---------------- kernel 4/5: mma.sync GEMM  C = A * B^T -------------------
#define STG_BYTES 32768            // A 16KB + B 16KB
#define OFF_A 0
#define OFF_B 16384
#define GEMM_SMEM_BYTES (3 * STG_BYTES)   // 98304

__device__ __forceinline__ void load_stage(
    uint32_t sbase, int buf,
    const __nv_bfloat16* __restrict__ Ah, const __nv_bfloat16* __restrict__ Al,
    const __nv_bfloat16* __restrict__ Bh, const __nv_bfloat16* __restrict__ Bl,
    int m0, int n0, int k0, int tid)
{
    const int row = tid >> 3;            // 0..31
    const int ch  = tid & 7;             // 16B chunk within 128B row
    const int kc  = (ch & 3) * 8;
    const bool lo = (ch >= 4);
    const uint32_t st = sbase + buf * STG_BYTES;
    const __nv_bfloat16* Asrc = lo ? Al : Ah;
    const __nv_bfloat16* Bsrc = lo ? Bl : Bh;
    #pragma unroll
    for (int h = 0; h < 4; ++h) {
        const int r = row + h * 32;
        const uint32_t so = swz128((uint32_t)(r * 128 + ch * 16));
        cp_async16(st + OFF_A + so, Asrc + (size_t)(m0 + r) * NN + k0 + kc);
        cp_async16(st + OFF_B + so, Bsrc + (size_t)(n0 + r) * NN + k0 + kc);
    }
}

// If Thi != null, also emits the transposed hi/lo split of C (for the next GEMM).
// Thi/Tlo MUST be distinct from Bh/Bl (no aliasing: other CTAs still read B).
__global__ __launch_bounds__(256, 2)
void mma_gemm_kernel(const __nv_bfloat16* __restrict__ Ah,
                     const __nv_bfloat16* __restrict__ Al,
                     const __nv_bfloat16* __restrict__ Bh,
                     const __nv_bfloat16* __restrict__ Bl,
                     float* __restrict__ C,
                     __nv_bfloat16* __restrict__ Thi,
                     __nv_bfloat16* __restrict__ Tlo) {
    extern __shared__ __align__(1024) char smem[];
    const uint32_t sbase = smem_to_u32(smem);
    const int tid  = threadIdx.x;
    const int lane = tid & 31;
    const int wid  = tid >> 5;
    const int wm   = wid & 1;
    const int wn   = wid >> 1;
    const int n0   = blockIdx.x * 128;   // grid.x over COLS (96)
    const int m0   = blockIdx.y * 128;   // grid.y over M (16)

    const int lr_a = lane & 15;
    const int kh_a = lane >> 4;
    const int lr_b = (lane & 7) | ((lane & 16) >> 1);
    const int kh_b = (lane >> 3) & 1;

    float4 acc[4][4];
    #pragma unroll
    for (int i = 0; i < 4; ++i)
        #pragma unroll
        for (int j = 0; j < 4; ++j) acc[i][j] = make_float4(0.f, 0.f, 0.f, 0.f);

    #pragma unroll
    for (int s = 0; s < 2; ++s) {
        load_stage(sbase, s, Ah, Al, Bh, Bl, m0, n0, s * 32, tid);
        CP_COMMIT();
    }

    const int NITER = NN / 32;           // 64
    int buf = 0, ldbuf = 2;
    for (int it = 0; it < NITER; ++it) {
        CP_WAIT1();
        __syncthreads();

        if (it + 2 < NITER)
            load_stage(sbase, ldbuf, Ah, Al, Bh, Bl, m0, n0, (it + 2) * 32, tid);
        CP_COMMIT();

        const uint32_t st = sbase + buf * STG_BYTES;
        #pragma unroll
        for (int ks = 0; ks < 2; ++ks) {
            uint32_t ah[4][4], al[4][4], bh[4][2], bl[4][2];
            #pragma unroll
            for (int mi = 0; mi < 4; ++mi) {
                const int r = wm * 64 + mi * 16 + lr_a;
                const uint32_t base = (uint32_t)(r * 128 + ks * 32 + kh_a * 16);
                ldmx4(ah[mi], st + OFF_A + swz128(base));
                ldmx4(al[mi], st + OFF_A + swz128(base + 64u));
            }
            #pragma unroll
            for (int nt = 0; nt < 2; ++nt) {
                const int r = wn * 32 + nt * 16 + lr_b;
                const uint32_t base = (uint32_t)(r * 128 + ks * 32 + kh_b * 16);
                uint32_t t[4];
                ldmx4(t, st + OFF_B + swz128(base));
                bh[nt * 2][0] = t[0]; bh[nt * 2][1] = t[1];
                bh[nt * 2 + 1][0] = t[2]; bh[nt * 2 + 1][1] = t[3];
                ldmx4(t, st + OFF_B + swz128(base + 64u));
                bl[nt * 2][0] = t[0]; bl[nt * 2][1] = t[1];
                bl[nt * 2 + 1][0] = t[2]; bl[nt * 2 + 1][1] = t[3];
            }
            #pragma unroll
            for (int mi = 0; mi < 4; ++mi)
                #pragma unroll
                for (int nj = 0; nj < 4; ++nj)
                    mma_bf16(acc[mi][nj], ah[mi], bh[nj]);
            #pragma unroll
            for (int mi = 0; mi < 4; ++mi)
                #pragma unroll
                for (int nj = 0; nj < 4; ++nj)
                    mma_bf16(acc[mi][nj], ah[mi], bl[nj]);
            #pragma unroll
            for (int mi = 0; mi < 4; ++mi)
                #pragma unroll
                for (int nj = 0; nj < 4; ++nj)
                    mma_bf16(acc[mi][nj], al[mi], bh[nj]);
        }

        buf   = (buf   + 1 == 3) ? 0 : buf   + 1;
        ldbuf = (ldbuf + 1 == 3) ? 0 : ldbuf + 1;
    }

    // fp32 epilogue (always)
    const int g  = lane >> 2;
    const int id = lane & 3;
    #pragma unroll
    for (int mi = 0; mi < 4; ++mi) {
        const int row = m0 + wm * 64 + mi * 16 + g;
        #pragma unroll
        for (int nj = 0; nj < 4; ++nj) {
            const int col = n0 + wn * 32 + nj * 8 + id * 2;
            float2* p0 = (float2*)(C + (size_t)row * COLS + col);
            float2* p1 = (float2*)(C + (size_t)(row + 8) * COLS + col);
            *p0 = make_float2(acc[mi][nj].x, acc[mi][nj].y);
            *p1 = make_float2(acc[mi][nj].z, acc[mi][nj].w);
        }
    }

    // fused transpose + hi/lo split of C tile into SEPARATE buffers
    if (Thi != nullptr) {
        __syncthreads();                 // mainloop smem reads complete
        float* ts = (float*)smem;        // [128][129] fp32, 66KB
        #pragma unroll
        for (int mi = 0; mi < 4; ++mi) {
            const int r = wm * 64 + mi * 16 + g;
            #pragma unroll
            for (int nj = 0; nj < 4; ++nj) {
                const int ccol = wn * 32 + nj * 8 + id * 2;
                ts[r * 129 + ccol]           = acc[mi][nj].x;
                ts[r * 129 + ccol + 1]       = acc[mi][nj].y;
                ts[(r + 8) * 129 + ccol]     = acc[mi][nj].z;
                ts[(r + 8) * 129 + ccol + 1] = acc[mi][nj].w;
            }
        }
        __syncthreads();
        #pragma unroll
        for (int cc = 0; cc < 16; ++cc) {
            const int c = wid * 16 + cc;
            #pragma unroll
            for (int rc = 0; rc < 4; ++rc) {
                const int r = rc * 32 + lane;
                const float v = ts[r * 129 + c];
                const __nv_bfloat16 h = __float2bfloat16(v);
                const size_t o = (size_t)(n0 + c) * NN + m0 + r;
                Thi[o] = h;
                Tlo[o] = __float2bfloat16(v - __bfloat162float(h));
            }
        }
    }
}

// ---------------- kernel 6: tensorized per-node grouped GEMM ---------------
// Smem: W panels [0,49152) copied from g_W; A panels [49152,98304); bias 98304.
#define FA_OFF    49152
#define FALO_OFF  24576
#define FBIAS_OFF 98304
#define FINAL_SMEM_BYTES 98560

__global__ __launch_bounds__(256, 2)
void final_mma_kernel(const float* __restrict__ emb, const char* __restrict__ Wg,
                      const float* __restrict__ bp,  const float* __restrict__ X,
                      const float* __restrict__ Y1,  const float* __restrict__ Y2,
                      float* __restrict__ out) {
    extern __shared__ __align__(1024) char fsm[];
    const uint32_t sb = smem_to_u32(fsm);
    float* biasS = (float*)(fsm + FBIAS_OFF);

    const int n    = blockIdx.x;
    const int tid  = threadIdx.x;
    const int lane = tid & 31;
    const int wid  = tid >> 5;
    const int wm   = wid & 3;            // 4 warps over M (48 rows each)
    const int wn   = wid >> 2;           // 2 warps over N (32 cols each)

    // async copy of this node's W panels (48KB, already swizzled)
    const char* wgn = Wg + (size_t)n * 49152;
    #pragma unroll
    for (int c = 0; c < 12; ++c) {
        const int ch = tid + c * 256;    // 0..3071
        cp_async16(sb + ch * 16, wgn + ch * 16);
    }
    CP_COMMIT();

    if (tid < DD) {
        float s = 0.0f;
        #pragma unroll
        for (int e = 0; e < EE; ++e)
            s = fmaf(emb[n * EE + e], bp[e * DD + tid], s);
        biasS[tid] = s;
    }

    const int lr_a = lane & 15;
    const int kh_a = lane >> 4;
    const int lr_b = (lane & 7) | ((lane & 16) >> 1);
    const int kh_b = (lane >> 3) & 1;

    float4 acc[3][4];
    #pragma unroll
    for (int i = 0; i < 3; ++i)
        #pragma unroll
        for (int j = 0; j < 4; ++j) acc[i][j] = make_float4(0.f, 0.f, 0.f, 0.f);

    const float* Xr  = X  + (size_t)n * COLS;
    const float* Y1r = Y1 + (size_t)n * COLS;
    const float* Y2r = Y2 + (size_t)n * COLS;

    CP_WAIT0();                          // this thread's W copies done

    #pragma unroll
    for (int kc = 0; kc < 3; ++kc) {
        // stage A_kc [192][64] -> hi/lo panels
        for (int idx = tid; idx < 6144; idx += 256) {
            const int r = idx >> 5, i0 = (idx & 31) * 2;
            float2 v;
            if (kc == 0)      v = *(const float2*)(Xr  + r * 64 + i0);
            else if (kc == 1) v = *(const float2*)(Y1r + r * 64 + i0);
            else {
                const float2 a = *(const float2*)(Y2r + r * 64 + i0);
                const float2 b = *(const float2*)(Xr  + r * 64 + i0);
                v.x = 2.0f * a.x - b.x; v.y = 2.0f * a.y - b.y;
            }
            const __nv_bfloat16 h0 = __float2bfloat16(v.x);
            const __nv_bfloat16 h1 = __float2bfloat16(v.y);
            const uint32_t off = swz128((uint32_t)(r * 128 + i0 * 2));
            *(uint32_t*)(fsm + FA_OFF + off) =
                pack_bf16(__bfloat162float(h0), __bfloat162float(h1));
            *(uint32_t*)(fsm + FA_OFF + FALO_OFF + off) =
                pack_bf16(v.x - __bfloat162float(h0), v.y - __bfloat162float(h1));
        }
        __syncthreads();                 // A staged + all W copies visible

        const uint32_t whB = sb + kc * 16384;
        const uint32_t wlB = whB + 8192;
        const uint32_t ahB = sb + FA_OFF;
        const uint32_t alB = ahB + FALO_OFF;
        #pragma unroll
        for (int ks = 0; ks < 4; ++ks) {
            uint32_t ah[3][4], al[3][4], bh[4][2], bl[4][2];
            #pragma unroll
            for (int mi = 0; mi < 3; ++mi) {
                const int r = wm * 48 + mi * 16 + lr_a;
                const uint32_t base = (uint32_t)(r * 128 + ks * 32 + kh_a * 16);
                ldmx4(ah[mi], ahB + swz128(base));
                ldmx4(al[mi], alB + swz128(base));
            }
            #pragma unroll
            for (int np = 0; np < 2; ++np) {
                const int o = wn * 32 + np * 16 + lr_b;
                const uint32_t base = (uint32_t)(o * 128 + ks * 32 + kh_b * 16);
                uint32_t t[4];
                ldmx4(t, whB + swz128(base));
                bh[np * 2][0] = t[0]; bh[np * 2][1] = t[1];
                bh[np * 2 + 1][0] = t[2]; bh[np * 2 + 1][1] = t[3];
                ldmx4(t, wlB + swz128(base));
                bl[np * 2][0] = t[0]; bl[np * 2][1] = t[1];
                bl[np * 2 + 1][0] = t[2]; bl[np * 2 + 1][1] = t[3];
            }
            #pragma unroll
            for (int mi = 0; mi < 3; ++mi)
                #pragma unroll
                for (int nj = 0; nj < 4; ++nj)
                    mma_bf16(acc[mi][nj], ah[mi], bh[nj]);
            #pragma unroll
            for (int mi = 0; mi < 3; ++mi)
                #pragma unroll
                for (int nj = 0; nj < 4; ++nj)
                    mma_bf16(acc[mi][nj], ah[mi], bl[nj]);
            #pragma unroll
            for (int mi = 0; mi < 3; ++mi)
                #pragma unroll
                for (int nj = 0; nj < 4; ++nj)
                    mma_bf16(acc[mi][nj], al[mi], bh[nj]);
        }
        __syncthreads();                 // protect A panels before restage
    }

    // epilogue: bias + scatter to out[B,N,T,D]
    const int g  = lane >> 2;
    const int id = lane & 3;
    #pragma unroll
    for (int mi = 0; mi < 3; ++mi) {
        const int r = wm * 48 + mi * 16 + g;
        #pragma unroll
        for (int nj = 0; nj < 4; ++nj) {
            const int o = wn * 32 + nj * 8 + id * 2;
            const float b0 = biasS[o], b1 = biasS[o + 1];
            {
                const int b = r / TT, t = r % TT;
                float2* p = (float2*)(out + ((size_t)(b * NN + n) * TT + t) * DD + o);
                *p = make_float2(acc[mi][nj].x + b0, acc[mi][nj].y + b1);
            }
            {
                const int r2 = r + 8;
                const int b = r2 / TT, t = r2 % TT;
                float2* p = (float2*)(out + ((size_t)(b * NN + n) * TT + t) * DD + o);
                *p = make_float2(acc[mi][nj].z + b0, acc[mi][nj].w + b1);
            }
        }
    }
}

// ---------------- launcher -------------------------------------------------
extern "C" void kernel_launch(void* const* d_in, const int* in_sizes, int n_in,
                              void* d_out, int out_size) {
    const float* x   = (const float*)d_in[0];   // [B,N,T,D]
    const float* emb = (const float*)d_in[1];   // [N,E]
    const float* wp  = (const float*)d_in[2];   // [E,K,D,D]
    const float* bp  = (const float*)d_in[3];   // [E,D]
    float* out = (float*)d_out;                 // [B,N,T,D]

    __nv_bfloat16 *Shi, *Slo, *Bhi, *Blo, *B2hi, *B2lo;
    float *X, *Y1, *Y2;
    char *Wg;
    cudaGetSymbolAddress((void**)&Shi,  g_Shi);
    cudaGetSymbolAddress((void**)&Slo,  g_Slo);
    cudaGetSymbolAddress((void**)&X,    g_X);
    cudaGetSymbolAddress((void**)&Bhi,  g_Bhi);
    cudaGetSymbolAddress((void**)&Blo,  g_Blo);
    cudaGetSymbolAddress((void**)&B2hi, g_B2hi);
    cudaGetSymbolAddress((void**)&B2lo, g_B2lo);
    cudaGetSymbolAddress((void**)&Y1,   g_Y1);
    cudaGetSymbolAddress((void**)&Y2,   g_Y2);
    cudaGetSymbolAddress((void**)&Wg,   g_W);

    cudaFuncSetAttribute(mma_gemm_kernel,
                         cudaFuncAttributeMaxDynamicSharedMemorySize,
                         GEMM_SMEM_BYTES);
    cudaFuncSetAttribute(final_mma_kernel,
                         cudaFuncAttributeMaxDynamicSharedMemorySize,
                         FINAL_SMEM_BYTES);

    support_kernel<<<NN, 256>>>(emb, Shi, Slo);

    dim3 tgrid(COLS / 32, NN / 32);
    dim3 ggrid(COLS / 128, NN / 128);
    dim3 wgrid(3, NN / 16);

    tsplitA_kernel<<<tgrid, 256>>>(x, X, Bhi, Blo);   // reshape + X^T split
    wprep_kernel<<<wgrid, 256>>>(emb, wp, Wg);        // hypernet weights -> panels
    mma_gemm_kernel<<<ggrid, 256, GEMM_SMEM_BYTES>>>(Shi, Slo, Bhi, Blo, Y1,
                                                     B2hi, B2lo); // fused Y1^T split
    mma_gemm_kernel<<<ggrid, 256, GEMM_SMEM_BYTES>>>(Shi, Slo, B2hi, B2lo, Y2,
                                                     nullptr, nullptr);
    final_mma_kernel<<<NN, 256, FINAL_SMEM_BYTES>>>(emb, Wg, bp, X, Y1, Y2, out);
}

// round 17
// speedup vs baseline: 5.0106x; 1.0101x over previous
#include <cuda_runtime.h>
#include <cuda_bf16.h>
#include <cstdint>

#define BATCH 16
#define NN    2048
#define TT    12
#define DD    64
#define EE    16
#define BTT   192            // BATCH * TT
#define COLS  12288          // BTT * DD

// ---------------- scratch (static device globals) --------------------------
__device__ __nv_bfloat16 g_Shi[(size_t)NN * NN];        // S hi  [N,N]
__device__ __nv_bfloat16 g_Slo[(size_t)NN * NN];        // S lo
__device__ float         g_X  [(size_t)NN * COLS];      // xr as [N, BT*D]
__device__ __nv_bfloat16 g_Bhi[(size_t)COLS * NN];      // X^T split hi
__device__ __nv_bfloat16 g_Blo[(size_t)COLS * NN];      // X^T split lo
__device__ __nv_bfloat16 g_B2hi[(size_t)COLS * NN];     // Y1^T split hi
__device__ __nv_bfloat16 g_B2lo[(size_t)COLS * NN];     // Y1^T split lo
__device__ __nv_bfloat16 g_A0h[(size_t)NN * COLS];      // X row-major split
__device__ __nv_bfloat16 g_A0l[(size_t)NN * COLS];
__device__ __nv_bfloat16 g_A1h[(size_t)NN * COLS];      // Y1 row-major split
__device__ __nv_bfloat16 g_A1l[(size_t)NN * COLS];
__device__ __nv_bfloat16 g_A2h[(size_t)NN * COLS];      // (2Y2-X) row-major split
__device__ __nv_bfloat16 g_A2l[(size_t)NN * COLS];
__device__ char          g_W  [(size_t)NN * 3 * 16384]; // per-node W panels

// ==================== helpers (baseline PTX only, safe on sm_103) ==========
__device__ __forceinline__ uint32_t smem_to_u32(const void* p) {
    uint32_t a;
    asm("{ .reg .u64 t; cvta.to.shared.u64 t, %1; cvt.u32.u64 %0, t; }"
        : "=r"(a) : "l"(p));
    return a;
}

// SW128 swizzle for 128-byte rows: bits[6:4] ^= bits[9:7]  (conflict-free)
__device__ __forceinline__ uint32_t swz128(uint32_t o) {
    return o ^ ((o >> 3) & 0x70u);
}

__device__ __forceinline__ void cp_async16(uint32_t saddr, const void* gaddr) {
    asm volatile("cp.async.cg.shared.global [%0], [%1], 16;"
                 :: "r"(saddr), "l"(gaddr));
}
#define CP_COMMIT() asm volatile("cp.async.commit_group;")
#define CP_WAIT1()  asm volatile("cp.async.wait_group 1;")
#define CP_WAIT0()  asm volatile("cp.async.wait_group 0;")

__device__ __forceinline__ void ldmx4(uint32_t r[4], uint32_t addr) {
    asm volatile("ldmatrix.sync.aligned.m8n8.x4.shared.b16 {%0,%1,%2,%3}, [%4];"
                 : "=r"(r[0]), "=r"(r[1]), "=r"(r[2]), "=r"(r[3]) : "r"(addr));
}

__device__ __forceinline__ void mma_bf16(float4& d, const uint32_t a[4],
                                         const uint32_t b[2]) {
    asm volatile(
        "mma.sync.aligned.m16n8k16.row.col.f32.bf16.bf16.f32 "
        "{%0,%1,%2,%3}, {%4,%5,%6,%7}, {%8,%9}, {%0,%1,%2,%3};"
        : "+f"(d.x), "+f"(d.y), "+f"(d.z), "+f"(d.w)
        : "r"(a[0]), "r"(a[1]), "r"(a[2]), "r"(a[3]), "r"(b[0]), "r"(b[1]));
}

__device__ __forceinline__ uint32_t pack_bf16(float x, float y) {
    __nv_bfloat162 t = __floats2bfloat162_rn(x, y);   // x -> low, y -> high
    return *(uint32_t*)&t;
}

// split v into (hi, lo) bf16 words packed pairwise
__device__ __forceinline__ void split2(float v0, float v1,
                                       uint32_t& hi, uint32_t& lo) {
    const __nv_bfloat16 h0 = __float2bfloat16(v0);
    const __nv_bfloat16 h1 = __float2bfloat16(v1);
    hi = pack_bf16(__bfloat162float(h0), __bfloat162float(h1));
    lo = pack_bf16(v0 - __bfloat162float(h0), v1 - __bfloat162float(h1));
}

// ---------------- kernel 1: supports = softmax(relu(E E^T)) -> hi/lo bf16 --
__global__ __launch_bounds__(256)
void support_kernel(const float* __restrict__ emb,
                    __nv_bfloat16* __restrict__ Shi,
                    __nv_bfloat16* __restrict__ Slo) {
    const int n   = blockIdx.x;
    const int tid = threadIdx.x;

    const float4* er = (const float4*)(emb + n * EE);
    const float4 e0 = er[0], e1 = er[1], e2 = er[2], e3 = er[3];

    float v[8];
    float mx = -1e30f;
    #pragma unroll
    for (int jj = 0; jj < 8; ++jj) {
        const int m = jj * 256 + tid;
        const float4* fm = (const float4*)(emb + m * EE);
        const float4 f0 = fm[0], f1 = fm[1], f2 = fm[2], f3 = fm[3];
        float d = e0.x*f0.x + e0.y*f0.y + e0.z*f0.z + e0.w*f0.w
                + e1.x*f1.x + e1.y*f1.y + e1.z*f1.z + e1.w*f1.w
                + e2.x*f2.x + e2.y*f2.y + e2.z*f2.z + e2.w*f2.w
                + e3.x*f3.x + e3.y*f3.y + e3.z*f3.z + e3.w*f3.w;
        d = fmaxf(d, 0.0f);
        v[jj] = d;
        mx = fmaxf(mx, d);
    }

    __shared__ float red[256];
    red[tid] = mx;
    __syncthreads();
    for (int s = 128; s > 0; s >>= 1) {
        if (tid < s) red[tid] = fmaxf(red[tid], red[tid + s]);
        __syncthreads();
    }
    mx = red[0];
    __syncthreads();

    float sum = 0.0f;
    #pragma unroll
    for (int jj = 0; jj < 8; ++jj) {
        v[jj] = expf(v[jj] - mx);
        sum += v[jj];
    }
    red[tid] = sum;
    __syncthreads();
    for (int s = 128; s > 0; s >>= 1) {
        if (tid < s) red[tid] += red[tid + s];
        __syncthreads();
    }
    const float inv = 1.0f / red[0];

    #pragma unroll
    for (int jj = 0; jj < 8; ++jj) {
        const float val = v[jj] * inv;
        const __nv_bfloat16 h = __float2bfloat16(val);
        const size_t o = (size_t)n * NN + jj * 256 + tid;
        Shi[o] = h;
        Slo[o] = __float2bfloat16(val - __bfloat162float(h));
    }
}

// ---------------- kernel 2: fused reshape + transpose + split --------------
// writes X fp32, X^T hi/lo (GEMM1 B), and X row-major hi/lo (final A0).
__global__ __launch_bounds__(256)
void tsplitA_kernel(const float* __restrict__ x, float* __restrict__ X,
                    __nv_bfloat16* __restrict__ hi,
                    __nv_bfloat16* __restrict__ lo,
                    __nv_bfloat16* __restrict__ A0h,
                    __nv_bfloat16* __restrict__ A0l) {
    __shared__ float tile[32][33];
    const int tx = threadIdx.x & 31;
    const int ty = threadIdx.x >> 5;     // 0..7
    const int c0 = blockIdx.x * 32;      // over COLS
    const int r0 = blockIdx.y * 32;      // over NN
    const int c  = c0 + tx;
    const int bt = c >> 6;
    const int d  = c & 63;
    const int b  = bt / TT;
    const int t  = bt % TT;
    #pragma unroll
    for (int j = 0; j < 4; ++j) {
        const int n = r0 + ty + j * 8;
        const float v = x[((size_t)(b * NN + n) * TT + t) * DD + d];
        X[(size_t)n * COLS + c] = v;
        const __nv_bfloat16 h = __float2bfloat16(v);
        A0h[(size_t)n * COLS + c] = h;
        A0l[(size_t)n * COLS + c] = __float2bfloat16(v - __bfloat162float(h));
        tile[ty + j * 8][tx] = v;
    }
    __syncthreads();
    #pragma unroll
    for (int j = 0; j < 4; ++j) {
        const int cc = ty + j * 8;
        const float v = tile[tx][cc];
        const __nv_bfloat16 h = __float2bfloat16(v);
        const size_t o = (size_t)(c0 + cc) * NN + r0 + tx;
        hi[o] = h;
        lo[o] = __float2bfloat16(v - __bfloat162float(h));
    }
}

// ---------------- kernel 3: hypernet weight precompute ---------------------
__global__ __launch_bounds__(256)
void wprep_kernel(const float* __restrict__ emb, const float* __restrict__ wp,
                  char* __restrict__ Wg) {
    __shared__ float wpS[16 * 512];      // [e][i(8)][o(64)]  32KB
    __shared__ float embS[16][16];
    const int k   = blockIdx.x;
    const int g   = blockIdx.y;
    const int tid = threadIdx.x;

    embS[tid >> 4][tid & 15] = emb[(g * 16 + (tid >> 4)) * EE + (tid & 15)];

    for (int ic = 0; ic < 8; ++ic) {     // 8 chunks of 8 i-rows
        __syncthreads();
        #pragma unroll
        for (int q = 0; q < 32; ++q) {
            const int idx = tid + q * 256;
            const int e = idx >> 9;
            const int rest = idx & 511;
            wpS[idx] = wp[e * 12288 + k * 4096 + ic * 512 + rest];
        }
        __syncthreads();
        #pragma unroll
        for (int q = 0; q < 4; ++q) {
            const int item = tid + q * 256;
            const int nl = item >> 6;
            const int o  = item & 63;
            float s[8];
            #pragma unroll
            for (int i = 0; i < 8; ++i) s[i] = 0.0f;
            #pragma unroll
            for (int e = 0; e < EE; ++e) {
                const float ev = embS[nl][e];
                #pragma unroll
                for (int i = 0; i < 8; ++i)
                    s[i] = fmaf(ev, wpS[e * 512 + i * 64 + o], s[i]);
            }
            uint32_t hi[4], lo[4];
            #pragma unroll
            for (int p = 0; p < 4; ++p)
                split2(s[2 * p], s[2 * p + 1], hi[p], lo[p]);
            char* base = Wg + ((size_t)(g * 16 + nl) * 3 + k) * 16384;
            const uint32_t off = swz128((uint32_t)(o * 128 + ic * 16));
            *(uint4*)(base + off)        = make_uint4(hi[0], hi[1], hi[2], hi[3]);
            *(uint4*)(base + 8192 + off) = make_uint4(lo[0], lo[1], lo[2], lo[3]);
        }
    }
}

// ---------------- kernel 4/5: mma.sync GEMM --------------------------------
// Outputs (no fp32 C): RowH/RowL = row-major split of (Xin ? 2*acc - X : acc);
// Thi/Tlo (nullable) = transposed split of acc (B operand for next GEMM).
#define STG_BYTES 32768            // A 16KB + B 16KB
#define OFF_A 0
#define OFF_B 16384
#define GEMM_SMEM_BYTES (3 * STG_BYTES)   // 98304

__device__ __forceinline__ void load_stage(
    uint32_t sbase, int buf,
    const __nv_bfloat16* __restrict__ Ah, const __nv_bfloat16* __restrict__ Al,
    const __nv_bfloat16* __restrict__ Bh, const __nv_bfloat16* __restrict__ Bl,
    int m0, int n0, int k0, int tid)
{
    const int row = tid >> 3;
    const int ch  = tid & 7;
    const int kc  = (ch & 3) * 8;
    const bool lo = (ch >= 4);
    const uint32_t st = sbase + buf * STG_BYTES;
    const __nv_bfloat16* Asrc = lo ? Al : Ah;
    const __nv_bfloat16* Bsrc = lo ? Bl : Bh;
    #pragma unroll
    for (int h = 0; h < 4; ++h) {
        const int r = row + h * 32;
        const uint32_t so = swz128((uint32_t)(r * 128 + ch * 16));
        cp_async16(st + OFF_A + so, Asrc + (size_t)(m0 + r) * NN + k0 + kc);
        cp_async16(st + OFF_B + so, Bsrc + (size_t)(n0 + r) * NN + k0 + kc);
    }
}

__global__ __launch_bounds__(256, 2)
void mma_gemm_kernel(const __nv_bfloat16* __restrict__ Ah,
                     const __nv_bfloat16* __restrict__ Al,
                     const __nv_bfloat16* __restrict__ Bh,
                     const __nv_bfloat16* __restrict__ Bl,
                     __nv_bfloat16* __restrict__ RowH,
                     __nv_bfloat16* __restrict__ RowL,
                     const float* __restrict__ Xin,
                     __nv_bfloat16* __restrict__ Thi,
                     __nv_bfloat16* __restrict__ Tlo) {
    extern __shared__ __align__(1024) char smem[];
    const uint32_t sbase = smem_to_u32(smem);
    const int tid  = threadIdx.x;
    const int lane = tid & 31;
    const int wid  = tid >> 5;
    const int wm   = wid & 1;
    const int wn   = wid >> 1;
    const int n0   = blockIdx.x * 128;   // grid.x over COLS (96)
    const int m0   = blockIdx.y * 128;   // grid.y over M (16)

    const int lr_a = lane & 15;
    const int kh_a = lane >> 4;
    const int lr_b = (lane & 7) | ((lane & 16) >> 1);
    const int kh_b = (lane >> 3) & 1;

    float4 acc[4][4];
    #pragma unroll
    for (int i = 0; i < 4; ++i)
        #pragma unroll
        for (int j = 0; j < 4; ++j) acc[i][j] = make_float4(0.f, 0.f, 0.f, 0.f);

    #pragma unroll
    for (int s = 0; s < 2; ++s) {
        load_stage(sbase, s, Ah, Al, Bh, Bl, m0, n0, s * 32, tid);
        CP_COMMIT();
    }

    const int NITER = NN / 32;           // 64
    int buf = 0, ldbuf = 2;
    for (int it = 0; it < NITER; ++it) {
        CP_WAIT1();
        __syncthreads();

        if (it + 2 < NITER)
            load_stage(sbase, ldbuf, Ah, Al, Bh, Bl, m0, n0, (it + 2) * 32, tid);
        CP_COMMIT();

        const uint32_t st = sbase + buf * STG_BYTES;
        #pragma unroll
        for (int ks = 0; ks < 2; ++ks) {
            uint32_t ah[4][4], al[4][4], bh[4][2], bl[4][2];
            #pragma unroll
            for (int mi = 0; mi < 4; ++mi) {
                const int r = wm * 64 + mi * 16 + lr_a;
                const uint32_t base = (uint32_t)(r * 128 + ks * 32 + kh_a * 16);
                ldmx4(ah[mi], st + OFF_A + swz128(base));
                ldmx4(al[mi], st + OFF_A + swz128(base + 64u));
            }
            #pragma unroll
            for (int nt = 0; nt < 2; ++nt) {
                const int r = wn * 32 + nt * 16 + lr_b;
                const uint32_t base = (uint32_t)(r * 128 + ks * 32 + kh_b * 16);
                uint32_t t[4];
                ldmx4(t, st + OFF_B + swz128(base));
                bh[nt * 2][0] = t[0]; bh[nt * 2][1] = t[1];
                bh[nt * 2 + 1][0] = t[2]; bh[nt * 2 + 1][1] = t[3];
                ldmx4(t, st + OFF_B + swz128(base + 64u));
                bl[nt * 2][0] = t[0]; bl[nt * 2][1] = t[1];
                bl[nt * 2 + 1][0] = t[2]; bl[nt * 2 + 1][1] = t[3];
            }
            #pragma unroll
            for (int mi = 0; mi < 4; ++mi)
                #pragma unroll
                for (int nj = 0; nj < 4; ++nj)
                    mma_bf16(acc[mi][nj], ah[mi], bh[nj]);
            #pragma unroll
            for (int mi = 0; mi < 4; ++mi)
                #pragma unroll
                for (int nj = 0; nj < 4; ++nj)
                    mma_bf16(acc[mi][nj], ah[mi], bl[nj]);
            #pragma unroll
            for (int mi = 0; mi < 4; ++mi)
                #pragma unroll
                for (int nj = 0; nj < 4; ++nj)
                    mma_bf16(acc[mi][nj], al[mi], bh[nj]);
        }

        buf   = (buf   + 1 == 3) ? 0 : buf   + 1;
        ldbuf = (ldbuf + 1 == 3) ? 0 : ldbuf + 1;
    }

    const int g  = lane >> 2;
    const int id = lane & 3;

    // row-major split epilogue (A panels for final kernel)
    #pragma unroll
    for (int mi = 0; mi < 4; ++mi) {
        const int row0 = m0 + wm * 64 + mi * 16 + g;
        const int row1 = row0 + 8;
        #pragma unroll
        for (int nj = 0; nj < 4; ++nj) {
            const int col = n0 + wn * 32 + nj * 8 + id * 2;
            float v0 = acc[mi][nj].x, v1 = acc[mi][nj].y;
            float v2 = acc[mi][nj].z, v3 = acc[mi][nj].w;
            if (Xin != nullptr) {
                const float2 x0 = *(const float2*)(Xin + (size_t)row0 * COLS + col);
                const float2 x1 = *(const float2*)(Xin + (size_t)row1 * COLS + col);
                v0 = 2.0f * v0 - x0.x; v1 = 2.0f * v1 - x0.y;
                v2 = 2.0f * v2 - x1.x; v3 = 2.0f * v3 - x1.y;
            }
            uint32_t h, l;
            split2(v0, v1, h, l);
            *(uint32_t*)(RowH + (size_t)row0 * COLS + col) = h;
            *(uint32_t*)(RowL + (size_t)row0 * COLS + col) = l;
            split2(v2, v3, h, l);
            *(uint32_t*)(RowH + (size_t)row1 * COLS + col) = h;
            *(uint32_t*)(RowL + (size_t)row1 * COLS + col) = l;
        }
    }

    // fused transpose + hi/lo split (B operand for next GEMM), separate bufs
    if (Thi != nullptr) {
        __syncthreads();
        float* ts = (float*)smem;        // [128][129] fp32
        #pragma unroll
        for (int mi = 0; mi < 4; ++mi) {
            const int r = wm * 64 + mi * 16 + g;
            #pragma unroll
            for (int nj = 0; nj < 4; ++nj) {
                const int ccol = wn * 32 + nj * 8 + id * 2;
                ts[r * 129 + ccol]           = acc[mi][nj].x;
                ts[r * 129 + ccol + 1]       = acc[mi][nj].y;
                ts[(r + 8) * 129 + ccol]     = acc[mi][nj].z;
                ts[(r + 8) * 129 + ccol + 1] = acc[mi][nj].w;
            }
        }
        __syncthreads();
        #pragma unroll
        for (int cc = 0; cc < 16; ++cc) {
            const int c = wid * 16 + cc;
            #pragma unroll
            for (int rc = 0; rc < 4; ++rc) {
                const int r = rc * 32 + lane;
                const float v = ts[r * 129 + c];
                const __nv_bfloat16 h = __float2bfloat16(v);
                const size_t o = (size_t)(n0 + c) * NN + m0 + r;
                Thi[o] = h;
                Tlo[o] = __float2bfloat16(v - __bfloat162float(h));
            }
        }
    }
}

// ---------------- kernel 6: pure copy + MMA grouped GEMM -------------------
// Smem: W panels [0,49152); A slot [49152,98304) (hi @ +0, lo @ +24576);
// bias @ 98304.
#define FA_OFF    49152
#define FALO_OFF  24576
#define FBIAS_OFF 98304
#define FINAL_SMEM_BYTES 98560

__global__ __launch_bounds__(256, 2)
void final_mma_kernel(const float* __restrict__ emb, const char* __restrict__ Wg,
                      const float* __restrict__ bp,
                      const __nv_bfloat16* __restrict__ A0h,
                      const __nv_bfloat16* __restrict__ A0l,
                      const __nv_bfloat16* __restrict__ A1h,
                      const __nv_bfloat16* __restrict__ A1l,
                      const __nv_bfloat16* __restrict__ A2h,
                      const __nv_bfloat16* __restrict__ A2l,
                      float* __restrict__ out) {
    extern __shared__ __align__(1024) char fsm[];
    const uint32_t sb = smem_to_u32(fsm);
    float* biasS = (float*)(fsm + FBIAS_OFF);

    const int n    = blockIdx.x;
    const int tid  = threadIdx.x;
    const int lane = tid & 31;
    const int wid  = tid >> 5;
    const int wm   = wid & 3;            // 4 warps over M (48 rows)
    const int wn   = wid >> 2;           // 2 warps over N (32 cols)

    const __nv_bfloat16* Ahs[3] = {A0h + (size_t)n * COLS,
                                   A1h + (size_t)n * COLS,
                                   A2h + (size_t)n * COLS};
    const __nv_bfloat16* Als[3] = {A0l + (size_t)n * COLS,
                                   A1l + (size_t)n * COLS,
                                   A2l + (size_t)n * COLS};

    // W panels (48KB, pre-swizzled) — linear copy
    const char* wgn = Wg + (size_t)n * 49152;
    #pragma unroll
    for (int c = 0; c < 12; ++c) {
        const int ch = tid + c * 256;    // 0..3071
        cp_async16(sb + ch * 16, wgn + ch * 16);
    }
    CP_COMMIT();

    // A panel kc=0 (24KB hi + 24KB lo) — swizzle applied on smem side
    #pragma unroll
    for (int c = 0; c < 6; ++c) {
        const uint32_t off = (uint32_t)(tid + c * 256) * 16;   // 0..24560
        const uint32_t so = swz128(off);
        cp_async16(sb + FA_OFF + so,            (const char*)Ahs[0] + off);
        cp_async16(sb + FA_OFF + FALO_OFF + so, (const char*)Als[0] + off);
    }
    CP_COMMIT();

    if (tid < DD) {
        float s = 0.0f;
        #pragma unroll
        for (int e = 0; e < EE; ++e)
            s = fmaf(emb[n * EE + e], bp[e * DD + tid], s);
        biasS[tid] = s;
    }

    const int lr_a = lane & 15;
    const int kh_a = lane >> 4;
    const int lr_b = (lane & 7) | ((lane & 16) >> 1);
    const int kh_b = (lane >> 3) & 1;

    float4 acc[3][4];
    #pragma unroll
    for (int i = 0; i < 3; ++i)
        #pragma unroll
        for (int j = 0; j < 4; ++j) acc[i][j] = make_float4(0.f, 0.f, 0.f, 0.f);

    #pragma unroll
    for (int kc = 0; kc < 3; ++kc) {
        CP_WAIT0();
        __syncthreads();                 // panel + W resident for all threads

        const uint32_t whB = sb + kc * 16384;
        const uint32_t wlB = whB + 8192;
        const uint32_t ahB = sb + FA_OFF;
        const uint32_t alB = ahB + FALO_OFF;
        #pragma unroll
        for (int ks = 0; ks < 4; ++ks) {
            uint32_t ah[3][4], al[3][4], bh[4][2], bl[4][2];
            #pragma unroll
            for (int mi = 0; mi < 3; ++mi) {
                const int r = wm * 48 + mi * 16 + lr_a;
                const uint32_t base = (uint32_t)(r * 128 + ks * 32 + kh_a * 16);
                ldmx4(ah[mi], ahB + swz128(base));
                ldmx4(al[mi], alB + swz128(base));
            }
            #pragma unroll
            for (int np = 0; np < 2; ++np) {
                const int o = wn * 32 + np * 16 + lr_b;
                const uint32_t base = (uint32_t)(o * 128 + ks * 32 + kh_b * 16);
                uint32_t t[4];
                ldmx4(t, whB + swz128(base));
                bh[np * 2][0] = t[0]; bh[np * 2][1] = t[1];
                bh[np * 2 + 1][0] = t[2]; bh[np * 2 + 1][1] = t[3];
                ldmx4(t, wlB + swz128(base));
                bl[np * 2][0] = t[0]; bl[np * 2][1] = t[1];
                bl[np * 2 + 1][0] = t[2]; bl[np * 2 + 1][1] = t[3];
            }
            #pragma unroll
            for (int mi = 0; mi < 3; ++mi)
                #pragma unroll
                for (int nj = 0; nj < 4; ++nj)
                    mma_bf16(acc[mi][nj], ah[mi], bh[nj]);
            #pragma unroll
            for (int mi = 0; mi < 3; ++mi)
                #pragma unroll
                for (int nj = 0; nj < 4; ++nj)
                    mma_bf16(acc[mi][nj], ah[mi], bl[nj]);
            #pragma unroll
            for (int mi = 0; mi < 3; ++mi)
                #pragma unroll
                for (int nj = 0; nj < 4; ++nj)
                    mma_bf16(acc[mi][nj], al[mi], bh[nj]);
        }
        __syncthreads();                 // A slot free before refill

        if (kc < 2) {
            #pragma unroll
            for (int c = 0; c < 6; ++c) {
                const uint32_t off = (uint32_t)(tid + c * 256) * 16;
                const uint32_t so = swz128(off);
                cp_async16(sb + FA_OFF + so,            (const char*)Ahs[kc + 1] + off);
                cp_async16(sb + FA_OFF + FALO_OFF + so, (const char*)Als[kc + 1] + off);
            }
            CP_COMMIT();
        }
    }

    // epilogue: bias + scatter to out[B,N,T,D]
    const int g  = lane >> 2;
    const int id = lane & 3;
    #pragma unroll
    for (int mi = 0; mi < 3; ++mi) {
        const int r = wm * 48 + mi * 16 + g;
        #pragma unroll
        for (int nj = 0; nj < 4; ++nj) {
            const int o = wn * 32 + nj * 8 + id * 2;
            const float b0 = biasS[o], b1 = biasS[o + 1];
            {
                const int b = r / TT, t = r % TT;
                float2* p = (float2*)(out + ((size_t)(b * NN + n) * TT + t) * DD + o);
                *p = make_float2(acc[mi][nj].x + b0, acc[mi][nj].y + b1);
            }
            {
                const int r2 = r + 8;
                const int b = r2 / TT, t = r2 % TT;
                float2* p = (float2*)(out + ((size_t)(b * NN + n) * TT + t) * DD + o);
                *p = make_float2(acc[mi][nj].z + b0, acc[mi][nj].w + b1);
            }
        }
    }
}

// ---------------- launcher -------------------------------------------------
extern "C" void kernel_launch(void* const* d_in, const int* in_sizes, int n_in,
                              void* d_out, int out_size) {
    const float* x   = (const float*)d_in[0];   // [B,N,T,D]
    const float* emb = (const float*)d_in[1];   // [N,E]
    const float* wp  = (const float*)d_in[2];   // [E,K,D,D]
    const float* bp  = (const float*)d_in[3];   // [E,D]
    float* out = (float*)d_out;                 // [B,N,T,D]

    __nv_bfloat16 *Shi, *Slo, *Bhi, *Blo, *B2hi, *B2lo;
    __nv_bfloat16 *A0h, *A0l, *A1h, *A1l, *A2h, *A2l;
    float *X;
    char *Wg;
    cudaGetSymbolAddress((void**)&Shi,  g_Shi);
    cudaGetSymbolAddress((void**)&Slo,  g_Slo);
    cudaGetSymbolAddress((void**)&X,    g_X);
    cudaGetSymbolAddress((void**)&Bhi,  g_Bhi);
    cudaGetSymbolAddress((void**)&Blo,  g_Blo);
    cudaGetSymbolAddress((void**)&B2hi, g_B2hi);
    cudaGetSymbolAddress((void**)&B2lo, g_B2lo);
    cudaGetSymbolAddress((void**)&A0h,  g_A0h);
    cudaGetSymbolAddress((void**)&A0l,  g_A0l);
    cudaGetSymbolAddress((void**)&A1h,  g_A1h);
    cudaGetSymbolAddress((void**)&A1l,  g_A1l);
    cudaGetSymbolAddress((void**)&A2h,  g_A2h);
    cudaGetSymbolAddress((void**)&A2l,  g_A2l);
    cudaGetSymbolAddress((void**)&Wg,   g_W);

    cudaFuncSetAttribute(mma_gemm_kernel,
                         cudaFuncAttributeMaxDynamicSharedMemorySize,
                         GEMM_SMEM_BYTES);
    cudaFuncSetAttribute(final_mma_kernel,
                         cudaFuncAttributeMaxDynamicSharedMemorySize,
                         FINAL_SMEM_BYTES);

    support_kernel<<<NN, 256>>>(emb, Shi, Slo);

    dim3 tgrid(COLS / 32, NN / 32);
    dim3 ggrid(COLS / 128, NN / 128);
    dim3 wgrid(3, NN / 16);

    tsplitA_kernel<<<tgrid, 256>>>(x, X, Bhi, Blo, A0h, A0l);
    wprep_kernel<<<wgrid, 256>>>(emb, wp, Wg);
    // GEMM1: S @ X -> A1 row split + Y1^T split (B2)
    mma_gemm_kernel<<<ggrid, 256, GEMM_SMEM_BYTES>>>(Shi, Slo, Bhi, Blo,
                                                     A1h, A1l, nullptr,
                                                     B2hi, B2lo);
    // GEMM2: S @ Y1 -> A2 = 2*acc - X row split, no transpose
    mma_gemm_kernel<<<ggrid, 256, GEMM_SMEM_BYTES>>>(Shi, Slo, B2hi, B2lo,
                                                     A2h, A2l, X,
                                                     nullptr, nullptr);
    final_mma_kernel<<<NN, 256, FINAL_SMEM_BYTES>>>(emb, Wg, bp,
                                                    A0h, A0l, A1h, A1l,
                                                    A2h, A2l, out);
}